// round 4
// baseline (speedup 1.0000x reference)
#include <cuda_runtime.h>
#include <cuda_bf16.h>

// Shapes (fixed by the problem)
#define B_  2
#define T_  512
#define N_  512
#define H_  64
#define S_  8
#define C_  8

// Edge-kernel tiling
#define TI 16      // i per block
#define TJ 8       // j per block  (E = TI*TJ = 128 edges/block)
#define HC 16      // h chunk (4 chunks of 16 cover H=64)

// ---------------------------------------------------------------------------
// Device scratch (no allocations allowed)
// ---------------------------------------------------------------------------
__device__ float g_repr[B_ * N_ * H_];   // node_repr
__device__ float g_Ai  [B_ * N_ * H_];   // repr @ W3[0:64]   + b3
__device__ float g_Bj  [B_ * N_ * H_];   // repr @ W3[64:128]
__device__ float g_prior[N_ * N_];
__device__ float g_deg [B_ * N_];        // degree, then inv-sqrt in place

// ---------------------------------------------------------------------------
// K0: zero degrees
// ---------------------------------------------------------------------------
__global__ void k_zero_deg() {
    g_deg[blockIdx.x * 512 + threadIdx.x] = 0.0f;
}

// ---------------------------------------------------------------------------
// K1: dynamic context reduction over T + 2-layer node MLP -> g_repr
// grid (N/32, B), block (32 n-lanes, 8 t-rows)
// ---------------------------------------------------------------------------
__global__ void k_context_mlp(const float* __restrict__ x,
                              const float* __restrict__ mask,
                              const float* __restrict__ statc,
                              const float* __restrict__ W1,
                              const float* __restrict__ b1,
                              const float* __restrict__ W2,
                              const float* __restrict__ b2) {
    const int tx = threadIdx.x;          // node lane 0..31
    const int ty = threadIdx.y;          // 0..7
    const int b  = blockIdx.y;
    const int n  = blockIdx.x * 32 + tx;

    __shared__ float s_sum[8][33], s_sq[8][33], s_cnt[8][33], s_ms[8][33];
    __shared__ int   s_last[8][33];
    __shared__ float s_f[32][13];        // feats: 4 dynamic + 8 static
    __shared__ float s_h[32][65];        // hidden layer

    const float* xb = x    + (size_t)b * T_ * N_;
    const float* mb = mask + (size_t)b * T_ * N_;

    float sum = 0.f, sq = 0.f, cnt = 0.f, ms = 0.f;
    int   lastt = 0;
    #pragma unroll 8
    for (int t = ty; t < T_; t += 8) {
        float xv = xb[t * N_ + n];
        float mv = mb[t * N_ + n];
        float ob = 1.0f - mv;
        sum += xv * ob;
        sq  += xv * xv * ob;
        cnt += ob;
        ms  += mv;
        if (ob > 0.5f) lastt = t;        // loop ascending -> final = max obs t
    }
    s_sum[ty][tx] = sum; s_sq[ty][tx] = sq; s_cnt[ty][tx] = cnt;
    s_ms[ty][tx] = ms;   s_last[ty][tx] = lastt;
    __syncthreads();

    if (ty == 0) {
        for (int r = 1; r < 8; r++) {
            sum += s_sum[r][tx]; sq += s_sq[r][tx]; cnt += s_cnt[r][tx];
            ms  += s_ms[r][tx];
            lastt = max(lastt, s_last[r][tx]);
        }
        float count = fmaxf(cnt, 1.0f);
        float mean  = sum / count;
        // sum_obs (x-mean)^2 = sq - 2 mean sum + mean^2 cnt  (exact in all cases)
        float var   = (sq - 2.0f * mean * sum + mean * mean * cnt) / count;
        float stdv  = sqrtf(fmaxf(var, 0.0f) + 1e-6f);
        float last  = xb[lastt * N_ + n];
        float mr    = ms * (1.0f / (float)T_);
        s_f[tx][0] = mean; s_f[tx][1] = stdv; s_f[tx][2] = last; s_f[tx][3] = mr;
        #pragma unroll
        for (int s = 0; s < S_; s++) s_f[tx][4 + s] = statc[n * S_ + s];
    }
    __syncthreads();

    // layer 1: feats(12) @ W1(12,64) -> relu
    #pragma unroll
    for (int ko = 0; ko < 8; ko++) {
        int k = ty * 8 + ko;
        float a = b1[k];
        #pragma unroll
        for (int f = 0; f < 12; f++) a += s_f[tx][f] * W1[f * 64 + k];
        s_h[tx][k] = fmaxf(a, 0.0f);
    }
    __syncthreads();

    // layer 2: h(64) @ W2(64,64) -> relu -> g_repr
    #pragma unroll
    for (int ko = 0; ko < 8; ko++) {
        int k = ty * 8 + ko;
        float a = b2[k];
        #pragma unroll
        for (int h = 0; h < 64; h++) a += s_h[tx][h] * W2[h * 64 + k];
        g_repr[((b * N_) + n) * H_ + k] = fmaxf(a, 0.0f);
    }
}

// ---------------------------------------------------------------------------
// K2: per-node precompute Ai = repr@W3a + b3, Bj = repr@W3b
// grid 256, block 256 (64 k-lanes x 4 nodes)
// ---------------------------------------------------------------------------
__global__ void k_aibj(const float* __restrict__ W3,
                       const float* __restrict__ b3) {
    __shared__ float w[128 * 64];        // W3 rows 0..127 (a then b), 32KB
    __shared__ float rsh[4][65];

    const int tid = threadIdx.x;
    for (int idx = tid; idx < 128 * 64; idx += 256) w[idx] = W3[idx];

    const int tx = tid & 63;             // k
    const int nl = tid >> 6;             // node-in-block
    const int ng = blockIdx.x * 4 + nl;  // flat (b*N + n), 0..1023
    rsh[nl][tx] = g_repr[ng * H_ + tx];
    __syncthreads();

    float a = b3[tx], bj = 0.0f;
    #pragma unroll
    for (int h = 0; h < 64; h++) {
        float r = rsh[nl][h];
        a  += r * w[h * 64 + tx];
        bj += r * w[(64 + h) * 64 + tx];
    }
    g_Ai[ng * H_ + tx] = a;
    g_Bj[ng * H_ + tx] = bj;
}

// ---------------------------------------------------------------------------
// K3: prior adjacency from node coords
// ---------------------------------------------------------------------------
__global__ void k_prior(const float* __restrict__ coords) {
    const int j = blockIdx.x * 16 + threadIdx.x;
    const int i = blockIdx.y * 16 + threadIdx.y;
    float d2 = 0.0f;
    #pragma unroll
    for (int c = 0; c < C_; c++) {
        float d = coords[i * C_ + c] - coords[j * C_ + c];
        d2 += d * d;
    }
    float pr = (i == j) ? 0.0f : 1.0f / (1.0f + sqrtf(d2));
    g_prior[i * N_ + j] = pr;
}

// ---------------------------------------------------------------------------
// K4: edge MLP (the hot kernel).
//   e_k = relu(Ai[i,k] + Bj[j,k] + sum_h |hi-hj|*W3c[h,k] + (hi*hj)*W3d[h,k])
//   edge = relu(e @ W4 + b4);  adapt = edge*prior + eye
// Tile: 16 i x 8 j = 128 edges/block.  D,P materialized transposed [h][e] in
// smem (h chunked by 16), then register-tiled dual GEMM: thread = 4e x 8k.
// grid (N/TJ, N/TI, B), block 256.
// ---------------------------------------------------------------------------
__global__ __launch_bounds__(256)
void k_edge(const float* __restrict__ W3,
            const float* __restrict__ W4,
            const float* __restrict__ b4p,
            float* __restrict__ out) {
    __shared__ float Dsh[HC][128];       // |hi-hj| chunk, [h][e]
    __shared__ float Psh[HC][128];       // hi*hj chunk
    __shared__ float Wc[HC][64];         // W3c chunk [h][k]
    __shared__ float Wd[HC][64];         // W3d chunk
    __shared__ float hi [TI][65];
    __shared__ float hj [TJ][65];
    __shared__ float Ais[TI][65];
    __shared__ float Bjs[TJ][65];
    __shared__ float W4s[64];
    __shared__ float adsh[128];

    const int tid = threadIdx.x;
    const int b   = blockIdx.z;
    const int i0  = blockIdx.y * TI;
    const int j0  = blockIdx.x * TJ;

    const float* reprB = g_repr + (size_t)b * N_ * H_;

    // prologue: hi/hj/Ai/Bj/W4 tiles
    for (int t = tid; t < TI * 64; t += 256) {
        int il = t >> 6, h = t & 63;
        hi [il][h] = reprB[(i0 + il) * H_ + h];
        Ais[il][h] = g_Ai[((b * N_) + i0 + il) * H_ + h];
    }
    for (int t = tid; t < TJ * 64; t += 256) {
        int jl = t >> 6, h = t & 63;
        hj [jl][h] = reprB[(j0 + jl) * H_ + h];
        Bjs[jl][h] = g_Bj[((b * N_) + j0 + jl) * H_ + h];
    }
    if (tid < 64) W4s[tid] = W4[tid];

    const int eg = tid & 31;             // edge group: edges eg*4 .. eg*4+3
    const int kg = tid >> 5;             // k group:    k = kg*8 .. kg*8+7

    float acc[4][8];
    #pragma unroll
    for (int r = 0; r < 4; r++)
        #pragma unroll
        for (int k = 0; k < 8; k++) acc[r][k] = 0.0f;

    for (int hc = 0; hc < H_ / HC; hc++) {
        __syncthreads();                 // smem reuse fence (prev chunk readers)

        // W3 chunk: rows 128+hc*HC (abs part) and 192+hc*HC (prod part)
        {
            const float4* sc = (const float4*)(W3 + (128 + hc * HC) * 64);
            const float4* sd = (const float4*)(W3 + (192 + hc * HC) * 64);
            ((float4*)Wc)[tid] = sc[tid];    // 256 * float4 = 1024 floats
            ((float4*)Wd)[tid] = sd[tid];
        }
        // fill D,P transposed
        const int hbase = hc * HC;
        for (int idx = tid; idx < HC * 128; idx += 256) {
            int hh = idx >> 7, e = idx & 127;
            int il = e >> 3,  jl = e & 7;
            float a = hi[il][hbase + hh];
            float c = hj[jl][hbase + hh];
            Dsh[hh][e] = fabsf(a - c);
            Psh[hh][e] = a * c;
        }
        __syncthreads();

        // dual rank-1 GEMM: 64 FMA per 6 LDS.128 per thread
        #pragma unroll
        for (int hh = 0; hh < HC; hh++) {
            float4 d0 = *(const float4*)&Dsh[hh][eg * 4];
            float4 p0 = *(const float4*)&Psh[hh][eg * 4];
            float4 c0 = *(const float4*)&Wc[hh][kg * 8];
            float4 c1 = *(const float4*)&Wc[hh][kg * 8 + 4];
            float4 e0 = *(const float4*)&Wd[hh][kg * 8];
            float4 e1 = *(const float4*)&Wd[hh][kg * 8 + 4];
            float dv[4] = {d0.x, d0.y, d0.z, d0.w};
            float pv[4] = {p0.x, p0.y, p0.z, p0.w};
            float wc[8] = {c0.x, c0.y, c0.z, c0.w, c1.x, c1.y, c1.z, c1.w};
            float wd[8] = {e0.x, e0.y, e0.z, e0.w, e1.x, e1.y, e1.z, e1.w};
            #pragma unroll
            for (int r = 0; r < 4; r++)
                #pragma unroll
                for (int k = 0; k < 8; k++)
                    acc[r][k] += dv[r] * wc[k] + pv[r] * wd[k];
        }
    }

    // epilogue: add Ai+Bj, relu, dot with W4 (partial over this thread's 8 k)
    const float b4v = b4p[0];
    float s[4];
    #pragma unroll
    for (int r = 0; r < 4; r++) {
        int e = eg * 4 + r;
        int il = e >> 3, jl = e & 7;
        float t = 0.0f;
        #pragma unroll
        for (int k = 0; k < 8; k++) {
            int kk = kg * 8 + k;
            float ev = acc[r][k] + Ais[il][kk] + Bjs[jl][kk];
            ev = fmaxf(ev, 0.0f);
            t += ev * W4s[kk];
        }
        s[r] = t;
    }
    __syncthreads();
    float* part = &Dsh[0][0];            // reuse: [kg][e] partials (1024 floats)
    #pragma unroll
    for (int r = 0; r < 4; r++) part[kg * 128 + eg * 4 + r] = s[r];
    __syncthreads();

    if (tid < 128) {
        int e = tid, il = e >> 3, jl = e & 7;
        float t = 0.0f;
        #pragma unroll
        for (int g = 0; g < 8; g++) t += part[g * 128 + e];
        float edge = fmaxf(t + b4v, 0.0f);
        int i = i0 + il, j = j0 + jl;
        float ad = edge * g_prior[i * N_ + j] + ((i == j) ? 1.0f : 0.0f);
        out[((size_t)(b * N_) + i) * N_ + j] = ad;   // adapt (pre-normalization)
        adsh[e] = ad;
    }
    __syncthreads();

    if (tid < TI) {
        float dsum = 0.0f;
        #pragma unroll
        for (int jl = 0; jl < TJ; jl++) dsum += adsh[tid * TJ + jl];
        atomicAdd(&g_deg[b * N_ + i0 + tid], dsum);
    }
}

// ---------------------------------------------------------------------------
// K5: degree -> inv-sqrt in place
// ---------------------------------------------------------------------------
__global__ void k_invdeg() {
    int t = blockIdx.x * 512 + threadIdx.x;
    g_deg[t] = rsqrtf(fmaxf(g_deg[t], 1e-6f));
}

// ---------------------------------------------------------------------------
// K6: out *= inv_i * inv_j  (float4 over j)
// ---------------------------------------------------------------------------
__global__ void k_norm(float* __restrict__ out) {
    int idx = blockIdx.x * 256 + threadIdx.x;      // one float4 each
    int j4  = (idx & 127) * 4;                     // 128 quads per row
    int bi  = idx >> 7;                            // flat b*N+i, 0..1023
    float  inv_i = g_deg[bi];
    float4 invj  = *(const float4*)&g_deg[(bi & ~(N_ - 1)) + j4];
    float4 v = ((float4*)out)[idx];
    v.x *= inv_i * invj.x;
    v.y *= inv_i * invj.y;
    v.z *= inv_i * invj.z;
    v.w *= inv_i * invj.w;
    ((float4*)out)[idx] = v;
}

// ---------------------------------------------------------------------------
// launch
// ---------------------------------------------------------------------------
extern "C" void kernel_launch(void* const* d_in, const int* in_sizes, int n_in,
                              void* d_out, int out_size) {
    const float* x      = (const float*)d_in[0];
    const float* mask   = (const float*)d_in[1];
    const float* statc  = (const float*)d_in[2];
    const float* coords = (const float*)d_in[3];
    const float* W1     = (const float*)d_in[4];
    const float* b1     = (const float*)d_in[5];
    const float* W2     = (const float*)d_in[6];
    const float* b2     = (const float*)d_in[7];
    const float* W3     = (const float*)d_in[8];
    const float* b3     = (const float*)d_in[9];
    const float* W4     = (const float*)d_in[10];
    const float* b4     = (const float*)d_in[11];
    float* out = (float*)d_out;

    k_zero_deg<<<2, 512>>>();
    k_context_mlp<<<dim3(N_ / 32, B_), dim3(32, 8)>>>(x, mask, statc, W1, b1, W2, b2);
    k_aibj<<<(B_ * N_) / 4, 256>>>(W3, b3);
    k_prior<<<dim3(N_ / 16, N_ / 16), dim3(16, 16)>>>(coords);
    k_edge<<<dim3(N_ / TJ, N_ / TI, B_), 256>>>(W3, W4, b4, out);
    k_invdeg<<<2, 512>>>();
    k_norm<<<(B_ * N_ * N_ / 4) / 256, 256>>>(out);
}

// round 5
// speedup vs baseline: 1.3248x; 1.3248x over previous
#include <cuda_runtime.h>
#include <cuda_bf16.h>

// Shapes (fixed by the problem)
#define B_  2
#define T_  512
#define N_  512
#define H_  64
#define S_  8
#define C_  8

// Edge-kernel tiling
#define TI 16      // i per block
#define TJ 8       // j per block  (E = TI*TJ = 128 edges/block)
#define HC 16      // h chunk (4 chunks of 16 cover H=64)

// ---------------------------------------------------------------------------
// Packed f32x2 helpers (sm_100+ PTX; ptxas will not auto-fuse from C++)
// ---------------------------------------------------------------------------
__device__ __forceinline__ unsigned long long pack2(float a) {
    unsigned long long r;
    asm("mov.b64 %0, {%1, %1};" : "=l"(r) : "f"(a));
    return r;
}
__device__ __forceinline__ void fma2(unsigned long long& d,
                                     unsigned long long a,
                                     unsigned long long b) {
    asm("fma.rn.f32x2 %0, %1, %2, %0;" : "+l"(d) : "l"(a), "l"(b));
}
__device__ __forceinline__ void unpack2(unsigned long long v, float& lo, float& hi) {
    asm("mov.b64 {%0, %1}, %2;" : "=f"(lo), "=f"(hi) : "l"(v));
}

// ---------------------------------------------------------------------------
// Device scratch (no allocations allowed)
// ---------------------------------------------------------------------------
__device__ float g_repr[B_ * N_ * H_];   // node_repr
__device__ float g_Ai  [B_ * N_ * H_];   // repr @ W3[0:64]   + b3
__device__ float g_Bj  [B_ * N_ * H_];   // repr @ W3[64:128]
__device__ float g_prior[N_ * N_];
__device__ float g_deg [B_ * N_];        // degree, then inv-sqrt in place

// ---------------------------------------------------------------------------
// K0: zero degrees
// ---------------------------------------------------------------------------
__global__ void k_zero_deg() {
    g_deg[blockIdx.x * 512 + threadIdx.x] = 0.0f;
}

// ---------------------------------------------------------------------------
// K1: dynamic context reduction over T + 2-layer node MLP -> g_repr
// grid (N/32, B), block (32 n-lanes, 8 t-rows)
// ---------------------------------------------------------------------------
__global__ void k_context_mlp(const float* __restrict__ x,
                              const float* __restrict__ mask,
                              const float* __restrict__ statc,
                              const float* __restrict__ W1,
                              const float* __restrict__ b1,
                              const float* __restrict__ W2,
                              const float* __restrict__ b2) {
    const int tx = threadIdx.x;          // node lane 0..31
    const int ty = threadIdx.y;          // 0..7
    const int b  = blockIdx.y;
    const int n  = blockIdx.x * 32 + tx;

    __shared__ float s_sum[8][33], s_sq[8][33], s_cnt[8][33], s_ms[8][33];
    __shared__ int   s_last[8][33];
    __shared__ float s_f[32][13];        // feats: 4 dynamic + 8 static
    __shared__ float s_h[32][65];        // hidden layer

    const float* xb = x    + (size_t)b * T_ * N_;
    const float* mb = mask + (size_t)b * T_ * N_;

    float sum = 0.f, sq = 0.f, cnt = 0.f, ms = 0.f;
    int   lastt = 0;
    #pragma unroll 8
    for (int t = ty; t < T_; t += 8) {
        float xv = xb[t * N_ + n];
        float mv = mb[t * N_ + n];
        float ob = 1.0f - mv;
        sum += xv * ob;
        sq  += xv * xv * ob;
        cnt += ob;
        ms  += mv;
        if (ob > 0.5f) lastt = t;        // loop ascending -> final = max obs t
    }
    s_sum[ty][tx] = sum; s_sq[ty][tx] = sq; s_cnt[ty][tx] = cnt;
    s_ms[ty][tx] = ms;   s_last[ty][tx] = lastt;
    __syncthreads();

    if (ty == 0) {
        for (int r = 1; r < 8; r++) {
            sum += s_sum[r][tx]; sq += s_sq[r][tx]; cnt += s_cnt[r][tx];
            ms  += s_ms[r][tx];
            lastt = max(lastt, s_last[r][tx]);
        }
        float count = fmaxf(cnt, 1.0f);
        float mean  = sum / count;
        float var   = (sq - 2.0f * mean * sum + mean * mean * cnt) / count;
        float stdv  = sqrtf(fmaxf(var, 0.0f) + 1e-6f);
        float last  = xb[lastt * N_ + n];
        float mr    = ms * (1.0f / (float)T_);
        s_f[tx][0] = mean; s_f[tx][1] = stdv; s_f[tx][2] = last; s_f[tx][3] = mr;
        #pragma unroll
        for (int s = 0; s < S_; s++) s_f[tx][4 + s] = statc[n * S_ + s];
    }
    __syncthreads();

    // layer 1: feats(12) @ W1(12,64) -> relu
    #pragma unroll
    for (int ko = 0; ko < 8; ko++) {
        int k = ty * 8 + ko;
        float a = b1[k];
        #pragma unroll
        for (int f = 0; f < 12; f++) a += s_f[tx][f] * W1[f * 64 + k];
        s_h[tx][k] = fmaxf(a, 0.0f);
    }
    __syncthreads();

    // layer 2: h(64) @ W2(64,64) -> relu -> g_repr
    #pragma unroll
    for (int ko = 0; ko < 8; ko++) {
        int k = ty * 8 + ko;
        float a = b2[k];
        #pragma unroll
        for (int h = 0; h < 64; h++) a += s_h[tx][h] * W2[h * 64 + k];
        g_repr[((b * N_) + n) * H_ + k] = fmaxf(a, 0.0f);
    }
}

// ---------------------------------------------------------------------------
// K2: per-node precompute Ai = repr@W3a + b3, Bj = repr@W3b
// grid 256, block 256 (64 k-lanes x 4 nodes)
// ---------------------------------------------------------------------------
__global__ void k_aibj(const float* __restrict__ W3,
                       const float* __restrict__ b3) {
    __shared__ float w[128 * 64];        // W3 rows 0..127 (a then b), 32KB
    __shared__ float rsh[4][65];

    const int tid = threadIdx.x;
    for (int idx = tid; idx < 128 * 64; idx += 256) w[idx] = W3[idx];

    const int tx = tid & 63;             // k
    const int nl = tid >> 6;             // node-in-block
    const int ng = blockIdx.x * 4 + nl;  // flat (b*N + n), 0..1023
    rsh[nl][tx] = g_repr[ng * H_ + tx];
    __syncthreads();

    float a = b3[tx], bj = 0.0f;
    #pragma unroll
    for (int h = 0; h < 64; h++) {
        float r = rsh[nl][h];
        a  += r * w[h * 64 + tx];
        bj += r * w[(64 + h) * 64 + tx];
    }
    g_Ai[ng * H_ + tx] = a;
    g_Bj[ng * H_ + tx] = bj;
}

// ---------------------------------------------------------------------------
// K3: prior adjacency from node coords
// ---------------------------------------------------------------------------
__global__ void k_prior(const float* __restrict__ coords) {
    const int j = blockIdx.x * 16 + threadIdx.x;
    const int i = blockIdx.y * 16 + threadIdx.y;
    float d2 = 0.0f;
    #pragma unroll
    for (int c = 0; c < C_; c++) {
        float d = coords[i * C_ + c] - coords[j * C_ + c];
        d2 += d * d;
    }
    float pr = (i == j) ? 0.0f : 1.0f / (1.0f + sqrtf(d2));
    g_prior[i * N_ + j] = pr;
}

// ---------------------------------------------------------------------------
// K4: edge MLP (the hot kernel) — packed f32x2 mainloop.
//   e_k = relu(Ai[i,k] + Bj[j,k] + sum_h |hi-hj|*W3c[h,k] + (hi*hj)*W3d[h,k])
//   edge = relu(e @ W4 + b4);  adapt = edge*prior + eye
// Tile: 16 i x 8 j = 128 edges/block.  D,P materialized transposed [h][e] in
// smem (h chunked by 16).  Thread = 4 edges x 8 k; accumulator packed along
// k-pairs so Wc/Wd smem float4 loads are natively FFMA2 operands; only the
// 8 D/P broadcast scalars per hh need an explicit mov.b64 pack (alu pipe,
// dual-issues under the FFMA2 stream).
// grid (N/TJ, N/TI, B), block 256.
// ---------------------------------------------------------------------------
__global__ __launch_bounds__(256)
void k_edge(const float* __restrict__ W3,
            const float* __restrict__ W4,
            const float* __restrict__ b4p,
            float* __restrict__ out) {
    __shared__ float Dsh[HC][128];       // |hi-hj| chunk, [h][e]
    __shared__ float Psh[HC][128];       // hi*hj chunk
    __shared__ float Wc[HC][64];         // W3c chunk [h][k]
    __shared__ float Wd[HC][64];         // W3d chunk
    __shared__ float hi [TI][65];
    __shared__ float hj [TJ][65];
    __shared__ float Ais[TI][65];
    __shared__ float Bjs[TJ][65];
    __shared__ float W4s[64];
    __shared__ float adsh[128];

    const int tid = threadIdx.x;
    const int b   = blockIdx.z;
    const int i0  = blockIdx.y * TI;
    const int j0  = blockIdx.x * TJ;

    const float* reprB = g_repr + (size_t)b * N_ * H_;

    // prologue: hi/hj/Ai/Bj/W4 tiles
    for (int t = tid; t < TI * 64; t += 256) {
        int il = t >> 6, h = t & 63;
        hi [il][h] = reprB[(i0 + il) * H_ + h];
        Ais[il][h] = g_Ai[((b * N_) + i0 + il) * H_ + h];
    }
    for (int t = tid; t < TJ * 64; t += 256) {
        int jl = t >> 6, h = t & 63;
        hj [jl][h] = reprB[(j0 + jl) * H_ + h];
        Bjs[jl][h] = g_Bj[((b * N_) + j0 + jl) * H_ + h];
    }
    if (tid < 64) W4s[tid] = W4[tid];

    const int eg = tid & 31;             // edge group: edges eg*4 .. eg*4+3
    const int kg = tid >> 5;             // k group:    k = kg*8 .. kg*8+7

    // acc[r][kp]: edge r (of 4), packed k-pair kp (of 4) -> 32 scalar accums
    unsigned long long acc[4][4];
    #pragma unroll
    for (int r = 0; r < 4; r++)
        #pragma unroll
        for (int kp = 0; kp < 4; kp++) acc[r][kp] = 0ull;

    for (int hc = 0; hc < H_ / HC; hc++) {
        __syncthreads();                 // smem reuse fence (prev chunk readers)

        // W3 chunk: rows 128+hc*HC (abs part) and 192+hc*HC (prod part)
        {
            const float4* sc = (const float4*)(W3 + (128 + hc * HC) * 64);
            const float4* sd = (const float4*)(W3 + (192 + hc * HC) * 64);
            ((float4*)Wc)[tid] = sc[tid];    // 256 * float4 = 1024 floats
            ((float4*)Wd)[tid] = sd[tid];
        }
        // fill D,P transposed
        const int hbase = hc * HC;
        for (int idx = tid; idx < HC * 128; idx += 256) {
            int hh = idx >> 7, e = idx & 127;
            int il = e >> 3,  jl = e & 7;
            float a = hi[il][hbase + hh];
            float c = hj[jl][hbase + hh];
            Dsh[hh][e] = fabsf(a - c);
            Psh[hh][e] = a * c;
        }
        __syncthreads();

        // dual rank-1 GEMM, packed: 32 FFMA2 (=64 FMA) per hh per thread
        #pragma unroll
        for (int hh = 0; hh < HC; hh++) {
            float4 d0 = *(const float4*)&Dsh[hh][eg * 4];
            float4 p0 = *(const float4*)&Psh[hh][eg * 4];
            // weight k-pairs straight from smem, already packed (broadcast)
            ulonglong2 wcA = *(const ulonglong2*)&Wc[hh][kg * 8];
            ulonglong2 wcB = *(const ulonglong2*)&Wc[hh][kg * 8 + 4];
            ulonglong2 wdA = *(const ulonglong2*)&Wd[hh][kg * 8];
            ulonglong2 wdB = *(const ulonglong2*)&Wd[hh][kg * 8 + 4];
            unsigned long long dvp[4], pvp[4];
            dvp[0] = pack2(d0.x); dvp[1] = pack2(d0.y);
            dvp[2] = pack2(d0.z); dvp[3] = pack2(d0.w);
            pvp[0] = pack2(p0.x); pvp[1] = pack2(p0.y);
            pvp[2] = pack2(p0.z); pvp[3] = pack2(p0.w);
            #pragma unroll
            for (int r = 0; r < 4; r++) {
                fma2(acc[r][0], dvp[r], wcA.x);
                fma2(acc[r][0], pvp[r], wdA.x);
                fma2(acc[r][1], dvp[r], wcA.y);
                fma2(acc[r][1], pvp[r], wdA.y);
                fma2(acc[r][2], dvp[r], wcB.x);
                fma2(acc[r][2], pvp[r], wdB.x);
                fma2(acc[r][3], dvp[r], wcB.y);
                fma2(acc[r][3], pvp[r], wdB.y);
            }
        }
    }

    // epilogue: unpack, add Ai+Bj, relu, dot with W4 (partial over 8 k)
    const float b4v = b4p[0];
    float s[4];
    #pragma unroll
    for (int r = 0; r < 4; r++) {
        int e = eg * 4 + r;
        int il = e >> 3, jl = e & 7;
        float t = 0.0f;
        #pragma unroll
        for (int kp = 0; kp < 4; kp++) {
            float lo, hi_;
            unpack2(acc[r][kp], lo, hi_);
            int kk = kg * 8 + kp * 2;
            float e0 = fmaxf(lo  + Ais[il][kk]     + Bjs[jl][kk],     0.0f);
            float e1 = fmaxf(hi_ + Ais[il][kk + 1] + Bjs[jl][kk + 1], 0.0f);
            t += e0 * W4s[kk] + e1 * W4s[kk + 1];
        }
        s[r] = t;
    }
    __syncthreads();
    float* part = &Dsh[0][0];            // reuse: [kg][e] partials (1024 floats)
    #pragma unroll
    for (int r = 0; r < 4; r++) part[kg * 128 + eg * 4 + r] = s[r];
    __syncthreads();

    if (tid < 128) {
        int e = tid, il = e >> 3, jl = e & 7;
        float t = 0.0f;
        #pragma unroll
        for (int g = 0; g < 8; g++) t += part[g * 128 + e];
        float edge = fmaxf(t + b4v, 0.0f);
        int i = i0 + il, j = j0 + jl;
        float ad = edge * g_prior[i * N_ + j] + ((i == j) ? 1.0f : 0.0f);
        out[((size_t)(b * N_) + i) * N_ + j] = ad;   // adapt (pre-normalization)
        adsh[e] = ad;
    }
    __syncthreads();

    if (tid < TI) {
        float dsum = 0.0f;
        #pragma unroll
        for (int jl = 0; jl < TJ; jl++) dsum += adsh[tid * TJ + jl];
        atomicAdd(&g_deg[b * N_ + i0 + tid], dsum);
    }
}

// ---------------------------------------------------------------------------
// K5: degree -> inv-sqrt in place
// ---------------------------------------------------------------------------
__global__ void k_invdeg() {
    int t = blockIdx.x * 512 + threadIdx.x;
    g_deg[t] = rsqrtf(fmaxf(g_deg[t], 1e-6f));
}

// ---------------------------------------------------------------------------
// K6: out *= inv_i * inv_j  (float4 over j)
// ---------------------------------------------------------------------------
__global__ void k_norm(float* __restrict__ out) {
    int idx = blockIdx.x * 256 + threadIdx.x;      // one float4 each
    int j4  = (idx & 127) * 4;                     // 128 quads per row
    int bi  = idx >> 7;                            // flat b*N+i, 0..1023
    float  inv_i = g_deg[bi];
    float4 invj  = *(const float4*)&g_deg[(bi & ~(N_ - 1)) + j4];
    float4 v = ((float4*)out)[idx];
    v.x *= inv_i * invj.x;
    v.y *= inv_i * invj.y;
    v.z *= inv_i * invj.z;
    v.w *= inv_i * invj.w;
    ((float4*)out)[idx] = v;
}

// ---------------------------------------------------------------------------
// launch
// ---------------------------------------------------------------------------
extern "C" void kernel_launch(void* const* d_in, const int* in_sizes, int n_in,
                              void* d_out, int out_size) {
    const float* x      = (const float*)d_in[0];
    const float* mask   = (const float*)d_in[1];
    const float* statc  = (const float*)d_in[2];
    const float* coords = (const float*)d_in[3];
    const float* W1     = (const float*)d_in[4];
    const float* b1     = (const float*)d_in[5];
    const float* W2     = (const float*)d_in[6];
    const float* b2     = (const float*)d_in[7];
    const float* W3     = (const float*)d_in[8];
    const float* b3     = (const float*)d_in[9];
    const float* W4     = (const float*)d_in[10];
    const float* b4     = (const float*)d_in[11];
    float* out = (float*)d_out;

    k_zero_deg<<<2, 512>>>();
    k_context_mlp<<<dim3(N_ / 32, B_), dim3(32, 8)>>>(x, mask, statc, W1, b1, W2, b2);
    k_aibj<<<(B_ * N_) / 4, 256>>>(W3, b3);
    k_prior<<<dim3(N_ / 16, N_ / 16), dim3(16, 16)>>>(coords);
    k_edge<<<dim3(N_ / TJ, N_ / TI, B_), 256>>>(W3, W4, b4, out);
    k_invdeg<<<2, 512>>>();
    k_norm<<<(B_ * N_ * N_ / 4) / 256, 256>>>(out);
}

// round 6
// speedup vs baseline: 2.9083x; 2.1953x over previous
#include <cuda_runtime.h>
#include <cuda_bf16.h>

// Shapes (fixed by the problem)
#define B_  2
#define T_  512
#define N_  512
#define H_  64
#define S_  8
#define C_  8

// Edge-kernel tiling: block = 256 edges (32 i x 8 j), N=64 k, K=128
#define TIB 32
#define TJB 8

// ---------------------------------------------------------------------------
// tf32 helpers (sm_80+ PTX, valid on sm_103a)
// ---------------------------------------------------------------------------
__device__ __forceinline__ unsigned cvt_tf32(float f) {
    unsigned u;
    asm("cvt.rna.tf32.f32 %0, %1;" : "=r"(u) : "f"(f));
    return u;
}
__device__ __forceinline__ void mma_tf32(float* c, const unsigned* a, const unsigned* b) {
    asm("mma.sync.aligned.m16n8k8.row.col.f32.tf32.tf32.f32 "
        "{%0,%1,%2,%3}, {%4,%5,%6,%7}, {%8,%9}, {%0,%1,%2,%3};"
        : "+f"(c[0]), "+f"(c[1]), "+f"(c[2]), "+f"(c[3])
        : "r"(a[0]), "r"(a[1]), "r"(a[2]), "r"(a[3]), "r"(b[0]), "r"(b[1]));
}

// ---------------------------------------------------------------------------
// Device scratch (no allocations allowed)
// ---------------------------------------------------------------------------
__device__ float g_repr[B_ * N_ * H_];   // node_repr
__device__ float g_Ai  [B_ * N_ * H_];   // repr @ W3[0:64]   + b3
__device__ float g_Bj  [B_ * N_ * H_];   // repr @ W3[64:128]
__device__ float g_prior[N_ * N_];
__device__ float g_deg [B_ * N_];        // degree, then inv-sqrt in place
// W3c/W3d pre-converted to tf32 and pre-shuffled into mma B-fragment order:
// flat index = ((hp*8 + ntg)*32 + lane)*2 + p
__device__ float g_WfC[8 * 8 * 32 * 2];
__device__ float g_WfD[8 * 8 * 32 * 2];

// ---------------------------------------------------------------------------
// K0: zero degrees
// ---------------------------------------------------------------------------
__global__ void k_zero_deg() {
    g_deg[blockIdx.x * 512 + threadIdx.x] = 0.0f;
}

// ---------------------------------------------------------------------------
// K1: dynamic context reduction over T + 2-layer node MLP -> g_repr
// grid (N/32, B), block (32 n-lanes, 8 t-rows)
// ---------------------------------------------------------------------------
__global__ void k_context_mlp(const float* __restrict__ x,
                              const float* __restrict__ mask,
                              const float* __restrict__ statc,
                              const float* __restrict__ W1,
                              const float* __restrict__ b1,
                              const float* __restrict__ W2,
                              const float* __restrict__ b2) {
    const int tx = threadIdx.x;          // node lane 0..31
    const int ty = threadIdx.y;          // 0..7
    const int b  = blockIdx.y;
    const int n  = blockIdx.x * 32 + tx;

    __shared__ float s_sum[8][33], s_sq[8][33], s_cnt[8][33], s_ms[8][33];
    __shared__ int   s_last[8][33];
    __shared__ float s_f[32][13];        // feats: 4 dynamic + 8 static
    __shared__ float s_h[32][65];        // hidden layer

    const float* xb = x    + (size_t)b * T_ * N_;
    const float* mb = mask + (size_t)b * T_ * N_;

    float sum = 0.f, sq = 0.f, cnt = 0.f, ms = 0.f;
    int   lastt = 0;
    #pragma unroll 8
    for (int t = ty; t < T_; t += 8) {
        float xv = xb[t * N_ + n];
        float mv = mb[t * N_ + n];
        float ob = 1.0f - mv;
        sum += xv * ob;
        sq  += xv * xv * ob;
        cnt += ob;
        ms  += mv;
        if (ob > 0.5f) lastt = t;        // loop ascending -> final = max obs t
    }
    s_sum[ty][tx] = sum; s_sq[ty][tx] = sq; s_cnt[ty][tx] = cnt;
    s_ms[ty][tx] = ms;   s_last[ty][tx] = lastt;
    __syncthreads();

    if (ty == 0) {
        for (int r = 1; r < 8; r++) {
            sum += s_sum[r][tx]; sq += s_sq[r][tx]; cnt += s_cnt[r][tx];
            ms  += s_ms[r][tx];
            lastt = max(lastt, s_last[r][tx]);
        }
        float count = fmaxf(cnt, 1.0f);
        float mean  = sum / count;
        float var   = (sq - 2.0f * mean * sum + mean * mean * cnt) / count;
        float stdv  = sqrtf(fmaxf(var, 0.0f) + 1e-6f);
        float last  = xb[lastt * N_ + n];
        float mr    = ms * (1.0f / (float)T_);
        s_f[tx][0] = mean; s_f[tx][1] = stdv; s_f[tx][2] = last; s_f[tx][3] = mr;
        #pragma unroll
        for (int s = 0; s < S_; s++) s_f[tx][4 + s] = statc[n * S_ + s];
    }
    __syncthreads();

    // layer 1: feats(12) @ W1(12,64) -> relu
    #pragma unroll
    for (int ko = 0; ko < 8; ko++) {
        int k = ty * 8 + ko;
        float a = b1[k];
        #pragma unroll
        for (int f = 0; f < 12; f++) a += s_f[tx][f] * W1[f * 64 + k];
        s_h[tx][k] = fmaxf(a, 0.0f);
    }
    __syncthreads();

    // layer 2: h(64) @ W2(64,64) -> relu -> g_repr
    #pragma unroll
    for (int ko = 0; ko < 8; ko++) {
        int k = ty * 8 + ko;
        float a = b2[k];
        #pragma unroll
        for (int h = 0; h < 64; h++) a += s_h[tx][h] * W2[h * 64 + k];
        g_repr[((b * N_) + n) * H_ + k] = fmaxf(a, 0.0f);
    }
}

// ---------------------------------------------------------------------------
// K2: per-node precompute Ai = repr@W3a + b3, Bj = repr@W3b
// grid 256, block 256 (64 k-lanes x 4 nodes)
// ---------------------------------------------------------------------------
__global__ void k_aibj(const float* __restrict__ W3,
                       const float* __restrict__ b3) {
    __shared__ float w[128 * 64];        // W3 rows 0..127 (a then b), 32KB
    __shared__ float rsh[4][65];

    const int tid = threadIdx.x;
    for (int idx = tid; idx < 128 * 64; idx += 256) w[idx] = W3[idx];

    const int tx = tid & 63;             // k
    const int nl = tid >> 6;             // node-in-block
    const int ng = blockIdx.x * 4 + nl;  // flat (b*N + n), 0..1023
    rsh[nl][tx] = g_repr[ng * H_ + tx];
    __syncthreads();

    float a = b3[tx], bj = 0.0f;
    #pragma unroll
    for (int h = 0; h < 64; h++) {
        float r = rsh[nl][h];
        a  += r * w[h * 64 + tx];
        bj += r * w[(64 + h) * 64 + tx];
    }
    g_Ai[ng * H_ + tx] = a;
    g_Bj[ng * H_ + tx] = bj;
}

// ---------------------------------------------------------------------------
// K2b: pre-shuffle W3c/W3d into tf32 B-fragment order.
// For m16n8k8.row.col: b0 at (row = lane%4,     col = lane/4)
//                      b1 at (row = lane%4 + 4, col = lane/4)
// grid 16, block 256 -> one element pair index per thread (4096 each array)
// ---------------------------------------------------------------------------
__global__ void k_wprep(const float* __restrict__ W3) {
    int f = blockIdx.x * 256 + threadIdx.x;      // 0..4095
    int p    = f & 1;
    int lane = (f >> 1) & 31;
    int ntg  = (f >> 6) & 7;
    int hp   = f >> 9;
    int row  = hp * 8 + (lane & 3) + p * 4;      // K index within [0,64)
    int col  = ntg * 8 + (lane >> 2);            // n index
    g_WfC[f] = __uint_as_float(cvt_tf32(W3[(128 + row) * 64 + col]));
    g_WfD[f] = __uint_as_float(cvt_tf32(W3[(192 + row) * 64 + col]));
}

// ---------------------------------------------------------------------------
// K3: prior adjacency from node coords
// ---------------------------------------------------------------------------
__global__ void k_prior(const float* __restrict__ coords) {
    const int j = blockIdx.x * 16 + threadIdx.x;
    const int i = blockIdx.y * 16 + threadIdx.y;
    float d2 = 0.0f;
    #pragma unroll
    for (int c = 0; c < C_; c++) {
        float d = coords[i * C_ + c] - coords[j * C_ + c];
        d2 += d * d;
    }
    float pr = (i == j) ? 0.0f : 1.0f / (1.0f + sqrtf(d2));
    g_prior[i * N_ + j] = pr;
}

// ---------------------------------------------------------------------------
// K4: edge MLP via tf32 mma.sync.
//   pair[e,k] = sum_h |hi-hj| Wc[h,k] + (hi*hj) Wd[h,k]   (tf32 GEMM, K=128)
//   e_k = relu(pair + Ai[i,k] + Bj[j,k]);  edge = relu(e@W4 + b4)
//   adapt = edge*prior + eye
// Block tile: M=256 edges (32i x 8j), N=64, K=128. 8 warps = 4 m x 2 n.
// A fragments (D,P) built in registers straight from hi/hj smem; B fragments
// pre-shuffled (k_wprep) -> one conflict-free LDS.64 per fragment.
// grid (N/TJB, N/TIB, B), block 256.
// ---------------------------------------------------------------------------
__global__ __launch_bounds__(256)
void k_edge(const float* __restrict__ W4,
            const float* __restrict__ b4p,
            float* __restrict__ out) {
    __shared__ float s_hi[32][68];               // pad 68: conflict-free A builds
    __shared__ float s_hj[8][68];
    __shared__ float s_WfC[8][8][32][2];         // 16KB, reused as Ais later
    __shared__ float s_WfD[8][8][32][2];         // 16KB, reused as Bjs later
    __shared__ float s_part[2][256];
    __shared__ float s_ad[256];
    __shared__ float s_W4[64];

    const int tid = threadIdx.x;
    const int b   = blockIdx.z;
    const int i0  = blockIdx.y * TIB;
    const int j0  = blockIdx.x * TJB;
    const int bN  = b * N_;

    const float* reprB = g_repr + (size_t)bN * H_;

    // prologue
    for (int idx = tid; idx < 32 * 64; idx += 256)
        s_hi[idx >> 6][idx & 63] = reprB[(i0 + (idx >> 6)) * H_ + (idx & 63)];
    for (int idx = tid; idx < 8 * 64; idx += 256)
        s_hj[idx >> 6][idx & 63] = reprB[(j0 + (idx >> 6)) * H_ + (idx & 63)];
    {
        const float4* srcC = (const float4*)g_WfC;
        const float4* srcD = (const float4*)g_WfD;
        float4* dstC = (float4*)&s_WfC[0][0][0][0];
        float4* dstD = (float4*)&s_WfD[0][0][0][0];
        for (int idx = tid; idx < 1024; idx += 256) { dstC[idx] = srcC[idx]; dstD[idx] = srcD[idx]; }
    }
    if (tid < 64) s_W4[tid] = W4[tid];
    __syncthreads();

    const int wid = tid >> 5, lane = tid & 31;
    const int warp_m = wid & 3;                  // edges [warp_m*64, +64)
    const int warp_n = wid >> 2;                 // k [warp_n*32, +32)
    const int g = lane >> 2, t = lane & 3;

    float acc[4][4][4];
    #pragma unroll
    for (int mt = 0; mt < 4; mt++)
        #pragma unroll
        for (int nt = 0; nt < 4; nt++)
            #pragma unroll
            for (int q = 0; q < 4; q++) acc[mt][nt][q] = 0.0f;

    #pragma unroll
    for (int hp = 0; hp < 8; hp++) {             // h-octet = K-step pair
        const int h0 = hp * 8 + t, h1 = h0 + 4;
        const float hj0 = s_hj[g][h0], hj1 = s_hj[g][h1];
        unsigned aD[4][4], aP[4][4];
        #pragma unroll
        for (int mt = 0; mt < 4; mt++) {
            const int il0 = warp_m * 8 + mt * 2;
            float hi00 = s_hi[il0][h0],     hi01 = s_hi[il0][h1];
            float hi10 = s_hi[il0 + 1][h0], hi11 = s_hi[il0 + 1][h1];
            aD[mt][0] = cvt_tf32(fabsf(hi00 - hj0));
            aD[mt][1] = cvt_tf32(fabsf(hi10 - hj0));
            aD[mt][2] = cvt_tf32(fabsf(hi01 - hj1));
            aD[mt][3] = cvt_tf32(fabsf(hi11 - hj1));
            aP[mt][0] = cvt_tf32(hi00 * hj0);
            aP[mt][1] = cvt_tf32(hi10 * hj0);
            aP[mt][2] = cvt_tf32(hi01 * hj1);
            aP[mt][3] = cvt_tf32(hi11 * hj1);
        }
        #pragma unroll
        for (int nt = 0; nt < 4; nt++) {
            const int ntg = warp_n * 4 + nt;
            float2 bc = *(const float2*)&s_WfC[hp][ntg][lane][0];
            float2 bd = *(const float2*)&s_WfD[hp][ntg][lane][0];
            unsigned bC[2] = { __float_as_uint(bc.x), __float_as_uint(bc.y) };
            unsigned bD[2] = { __float_as_uint(bd.x), __float_as_uint(bd.y) };
            #pragma unroll
            for (int mt = 0; mt < 4; mt++) {
                mma_tf32(acc[mt][nt], aD[mt], bC);
                mma_tf32(acc[mt][nt], aP[mt], bD);
            }
        }
    }

    // restage Ai/Bj into smem reused from the weight-fragment buffers
    __syncthreads();
    float* s_Ais = &s_WfC[0][0][0][0];           // [32][64]
    float* s_Bjs = &s_WfD[0][0][0][0];           // [8][64]
    {
        const float4* srcA = (const float4*)(g_Ai + (size_t)(bN + i0) * H_);
        float4* dstA = (float4*)s_Ais;
        for (int idx = tid; idx < 512; idx += 256) dstA[idx] = srcA[idx];
        const float4* srcB = (const float4*)(g_Bj + (size_t)(bN + j0) * H_);
        float4* dstB = (float4*)s_Bjs;
        if (tid < 128) dstB[tid] = srcB[tid];
    }
    __syncthreads();

    // epilogue: e_k = relu(acc + Ai + Bj); partial dot with W4 over this
    // thread's k columns, then quad-reduce (t lanes) and cross-warp_n combine.
    float psum[4][2];
    #pragma unroll
    for (int mt = 0; mt < 4; mt++) {
        #pragma unroll
        for (int half = 0; half < 2; half++) {
            const int il = warp_m * 8 + mt * 2 + half;
            const int jl = g;
            float s = 0.0f;
            #pragma unroll
            for (int nt = 0; nt < 4; nt++) {
                const int k0 = warp_n * 32 + nt * 8 + 2 * t;
                float ab0 = s_Ais[il * 64 + k0]     + s_Bjs[jl * 64 + k0];
                float ab1 = s_Ais[il * 64 + k0 + 1] + s_Bjs[jl * 64 + k0 + 1];
                float v0 = fmaxf(acc[mt][nt][half * 2]     + ab0, 0.0f);
                float v1 = fmaxf(acc[mt][nt][half * 2 + 1] + ab1, 0.0f);
                s += v0 * s_W4[k0] + v1 * s_W4[k0 + 1];
            }
            psum[mt][half] = s;
        }
    }
    #pragma unroll
    for (int mt = 0; mt < 4; mt++) {
        #pragma unroll
        for (int half = 0; half < 2; half++) {
            float s = psum[mt][half];
            s += __shfl_xor_sync(0xffffffffu, s, 1);
            s += __shfl_xor_sync(0xffffffffu, s, 2);
            if (t == 0) {
                int e = warp_m * 64 + mt * 16 + g + half * 8;
                s_part[warp_n][e] = s;
            }
        }
    }
    __syncthreads();

    {
        const float b4v = b4p[0];
        int e  = tid;                            // 0..255
        int il = e >> 3, jl = e & 7;
        int i  = i0 + il, j = j0 + jl;
        float edge = fmaxf(s_part[0][e] + s_part[1][e] + b4v, 0.0f);
        float ad = edge * g_prior[i * N_ + j] + ((i == j) ? 1.0f : 0.0f);
        out[((size_t)(bN + i)) * N_ + j] = ad;   // adapt (pre-normalization)
        s_ad[e] = ad;
    }
    __syncthreads();

    if (tid < 32) {
        float dsum = 0.0f;
        #pragma unroll
        for (int jl = 0; jl < 8; jl++) dsum += s_ad[tid * 8 + jl];
        atomicAdd(&g_deg[bN + i0 + tid], dsum);
    }
}

// ---------------------------------------------------------------------------
// K5: degree -> inv-sqrt in place
// ---------------------------------------------------------------------------
__global__ void k_invdeg() {
    int t = blockIdx.x * 512 + threadIdx.x;
    g_deg[t] = rsqrtf(fmaxf(g_deg[t], 1e-6f));
}

// ---------------------------------------------------------------------------
// K6: out *= inv_i * inv_j  (float4 over j)
// ---------------------------------------------------------------------------
__global__ void k_norm(float* __restrict__ out) {
    int idx = blockIdx.x * 256 + threadIdx.x;      // one float4 each
    int j4  = (idx & 127) * 4;                     // 128 quads per row
    int bi  = idx >> 7;                            // flat b*N+i, 0..1023
    float  inv_i = g_deg[bi];
    float4 invj  = *(const float4*)&g_deg[(bi & ~(N_ - 1)) + j4];
    float4 v = ((float4*)out)[idx];
    v.x *= inv_i * invj.x;
    v.y *= inv_i * invj.y;
    v.z *= inv_i * invj.z;
    v.w *= inv_i * invj.w;
    ((float4*)out)[idx] = v;
}

// ---------------------------------------------------------------------------
// launch
// ---------------------------------------------------------------------------
extern "C" void kernel_launch(void* const* d_in, const int* in_sizes, int n_in,
                              void* d_out, int out_size) {
    const float* x      = (const float*)d_in[0];
    const float* mask   = (const float*)d_in[1];
    const float* statc  = (const float*)d_in[2];
    const float* coords = (const float*)d_in[3];
    const float* W1     = (const float*)d_in[4];
    const float* b1     = (const float*)d_in[5];
    const float* W2     = (const float*)d_in[6];
    const float* b2     = (const float*)d_in[7];
    const float* W3     = (const float*)d_in[8];
    const float* b3     = (const float*)d_in[9];
    const float* W4     = (const float*)d_in[10];
    const float* b4     = (const float*)d_in[11];
    float* out = (float*)d_out;

    k_zero_deg<<<2, 512>>>();
    k_wprep<<<16, 256>>>(W3);
    k_context_mlp<<<dim3(N_ / 32, B_), dim3(32, 8)>>>(x, mask, statc, W1, b1, W2, b2);
    k_aibj<<<(B_ * N_) / 4, 256>>>(W3, b3);
    k_prior<<<dim3(N_ / 16, N_ / 16), dim3(16, 16)>>>(coords);
    k_edge<<<dim3(N_ / TJB, N_ / TIB, B_), 256>>>(W4, b4, out);
    k_invdeg<<<2, 512>>>();
    k_norm<<<(B_ * N_ * N_ / 4) / 256, 256>>>(out);
}

// round 8
// speedup vs baseline: 2.9820x; 1.0253x over previous
#include <cuda_runtime.h>
#include <cuda_bf16.h>

// Shapes (fixed by the problem)
#define B_  2
#define T_  512
#define N_  512
#define H_  64
#define S_  8
#define C_  8

// Edge-kernel tiling: block = 256 edges (32 i x 8 j), N=64 k, K=128
#define TIB 32
#define TJB 8

// ---------------------------------------------------------------------------
// tf32 helpers (sm_80+ PTX, valid on sm_103a)
// ---------------------------------------------------------------------------
__device__ __forceinline__ unsigned cvt_tf32(float f) {
    unsigned u;
    asm("cvt.rna.tf32.f32 %0, %1;" : "=r"(u) : "f"(f));
    return u;
}
__device__ __forceinline__ void mma_tf32(float* c, const unsigned* a, const unsigned* b) {
    asm("mma.sync.aligned.m16n8k8.row.col.f32.tf32.tf32.f32 "
        "{%0,%1,%2,%3}, {%4,%5,%6,%7}, {%8,%9}, {%0,%1,%2,%3};"
        : "+f"(c[0]), "+f"(c[1]), "+f"(c[2]), "+f"(c[3])
        : "r"(a[0]), "r"(a[1]), "r"(a[2]), "r"(a[3]), "r"(b[0]), "r"(b[1]));
}

// ---------------------------------------------------------------------------
// Device scratch (no allocations allowed)
// ---------------------------------------------------------------------------
__device__ float g_repr[B_ * N_ * H_];   // node_repr
__device__ float g_Ai  [B_ * N_ * H_];   // repr @ W3[0:64]   + b3
__device__ float g_Bj  [B_ * N_ * H_];   // repr @ W3[64:128]
__device__ float g_deg [B_ * N_];        // degree accumulators
// per-node reduction stats
__device__ float g_s_sum[B_ * N_];
__device__ float g_s_sq [B_ * N_];
__device__ float g_s_cnt[B_ * N_];
__device__ float g_s_ms [B_ * N_];
__device__ int   g_s_last[B_ * N_];
// W3c/W3d pre-converted to tf32 and pre-shuffled into mma B-fragment order:
// flat index = ((hp*8 + ntg)*32 + lane)*2 + p
__device__ float g_WfC[8 * 8 * 32 * 2];
__device__ float g_WfD[8 * 8 * 32 * 2];

// ---------------------------------------------------------------------------
// K0: zero degree + stat accumulators. grid 2, block 512.
// ---------------------------------------------------------------------------
__global__ void k_zero() {
    int t = blockIdx.x * 512 + threadIdx.x;      // 0..1023
    g_deg[t] = 0.0f;
    g_s_sum[t] = 0.0f; g_s_sq[t] = 0.0f;
    g_s_cnt[t] = 0.0f; g_s_ms[t] = 0.0f;
    g_s_last[t] = 0;
}

// ---------------------------------------------------------------------------
// K1a: chip-wide T-chunked reduction. grid (N/32, B, 8), block (32, 8).
// Each block covers 64 timesteps for 32 nodes; partials via atomics.
// ---------------------------------------------------------------------------
__global__ void k_reduce(const float* __restrict__ x,
                         const float* __restrict__ mask) {
    const int tx = threadIdx.x, ty = threadIdx.y;
    const int b  = blockIdx.y;
    const int n  = blockIdx.x * 32 + tx;
    const int t0 = blockIdx.z * 64;

    __shared__ float s_sum[8][33], s_sq[8][33], s_cnt[8][33], s_ms[8][33];
    __shared__ int   s_last[8][33];

    const float* xb = x    + (size_t)b * T_ * N_;
    const float* mb = mask + (size_t)b * T_ * N_;

    float sum = 0.f, sq = 0.f, cnt = 0.f, ms = 0.f;
    int   lastt = -1;
    #pragma unroll
    for (int it = 0; it < 8; it++) {
        int t = t0 + ty + it * 8;
        float xv = xb[t * N_ + n];
        float mv = mb[t * N_ + n];
        float ob = 1.0f - mv;
        sum += xv * ob;
        sq  += xv * xv * ob;
        cnt += ob;
        ms  += mv;
        if (ob > 0.5f) lastt = t;
    }
    s_sum[ty][tx] = sum; s_sq[ty][tx] = sq; s_cnt[ty][tx] = cnt;
    s_ms[ty][tx] = ms;   s_last[ty][tx] = lastt;
    __syncthreads();

    if (ty == 0) {
        for (int r = 1; r < 8; r++) {
            sum += s_sum[r][tx]; sq += s_sq[r][tx]; cnt += s_cnt[r][tx];
            ms  += s_ms[r][tx];
            lastt = max(lastt, s_last[r][tx]);
        }
        int idx = b * N_ + n;
        atomicAdd(&g_s_sum[idx], sum);
        atomicAdd(&g_s_sq [idx], sq);
        atomicAdd(&g_s_cnt[idx], cnt);
        atomicAdd(&g_s_ms [idx], ms);
        if (lastt >= 0) atomicMax(&g_s_last[idx], lastt);
    }
}

// ---------------------------------------------------------------------------
// K1b: finalize stats + 2-layer node MLP -> g_repr.  grid (N/32, B), block (32,8)
// ---------------------------------------------------------------------------
__global__ void k_finalize_mlp(const float* __restrict__ x,
                               const float* __restrict__ statc,
                               const float* __restrict__ W1,
                               const float* __restrict__ b1,
                               const float* __restrict__ W2,
                               const float* __restrict__ b2) {
    const int tx = threadIdx.x, ty = threadIdx.y;
    const int b  = blockIdx.y;
    const int n  = blockIdx.x * 32 + tx;

    __shared__ float s_f[32][13];        // feats: 4 dynamic + 8 static
    __shared__ float s_h[32][65];        // hidden layer

    if (ty == 0) {
        int idx = b * N_ + n;
        float sum = g_s_sum[idx], sq = g_s_sq[idx];
        float cnt = g_s_cnt[idx], ms = g_s_ms[idx];
        int lastt = g_s_last[idx];
        float count = fmaxf(cnt, 1.0f);
        float mean  = sum / count;
        float var   = (sq - 2.0f * mean * sum + mean * mean * cnt) / count;
        float stdv  = sqrtf(fmaxf(var, 0.0f) + 1e-6f);
        float last  = x[((size_t)b * T_ + lastt) * N_ + n];
        float mr    = ms * (1.0f / (float)T_);
        s_f[tx][0] = mean; s_f[tx][1] = stdv; s_f[tx][2] = last; s_f[tx][3] = mr;
        #pragma unroll
        for (int s = 0; s < S_; s++) s_f[tx][4 + s] = statc[n * S_ + s];
    }
    __syncthreads();

    // layer 1: feats(12) @ W1(12,64) -> relu
    #pragma unroll
    for (int ko = 0; ko < 8; ko++) {
        int k = ty * 8 + ko;
        float a = b1[k];
        #pragma unroll
        for (int f = 0; f < 12; f++) a += s_f[tx][f] * W1[f * 64 + k];
        s_h[tx][k] = fmaxf(a, 0.0f);
    }
    __syncthreads();

    // layer 2: h(64) @ W2(64,64) -> relu -> g_repr
    #pragma unroll
    for (int ko = 0; ko < 8; ko++) {
        int k = ty * 8 + ko;
        float a = b2[k];
        #pragma unroll
        for (int h = 0; h < 64; h++) a += s_h[tx][h] * W2[h * 64 + k];
        g_repr[((b * N_) + n) * H_ + k] = fmaxf(a, 0.0f);
    }
}

// ---------------------------------------------------------------------------
// K2: per-node precompute Ai = repr@W3a + b3, Bj = repr@W3b
// grid 64, block 256: 16 nodes/block (4x better W3-stage amortization)
// ---------------------------------------------------------------------------
__global__ void k_aibj(const float* __restrict__ W3,
                       const float* __restrict__ b3) {
    __shared__ float w[128 * 64];        // W3 rows 0..127 (a then b), 32KB
    __shared__ float rsh[16][65];

    const int tid = threadIdx.x;
    for (int idx = tid; idx < 128 * 64; idx += 256) w[idx] = W3[idx];

    const int ng0 = blockIdx.x * 16;     // flat (b*N + n) base
    for (int idx = tid; idx < 16 * 64; idx += 256)
        rsh[idx >> 6][idx & 63] = g_repr[(ng0 + (idx >> 6)) * H_ + (idx & 63)];
    __syncthreads();

    const int tx = tid & 63;             // k
    const float b3v = b3[tx];
    for (int nl = tid >> 6; nl < 16; nl += 4) {
        float a = b3v, bj = 0.0f;
        #pragma unroll
        for (int h = 0; h < 64; h++) {
            float r = rsh[nl][h];
            a  += r * w[h * 64 + tx];
            bj += r * w[(64 + h) * 64 + tx];
        }
        g_Ai[(ng0 + nl) * H_ + tx] = a;
        g_Bj[(ng0 + nl) * H_ + tx] = bj;
    }
}

// ---------------------------------------------------------------------------
// K2b: pre-shuffle W3c/W3d into tf32 B-fragment order.
// For m16n8k8.row.col: b0 at (row = lane%4,     col = lane/4)
//                      b1 at (row = lane%4 + 4, col = lane/4)
// grid 16, block 256 -> one element pair index per thread (4096 each array)
// ---------------------------------------------------------------------------
__global__ void k_wprep(const float* __restrict__ W3) {
    int f = blockIdx.x * 256 + threadIdx.x;      // 0..4095
    int p    = f & 1;
    int lane = (f >> 1) & 31;
    int ntg  = (f >> 6) & 7;
    int hp   = f >> 9;
    int row  = hp * 8 + (lane & 3) + p * 4;      // K index within [0,64)
    int col  = ntg * 8 + (lane >> 2);            // n index
    g_WfC[f] = __uint_as_float(cvt_tf32(W3[(128 + row) * 64 + col]));
    g_WfD[f] = __uint_as_float(cvt_tf32(W3[(192 + row) * 64 + col]));
}

// ---------------------------------------------------------------------------
// K4: edge MLP via tf32 mma.sync; prior computed inline from coords.
//   pair[e,k] = sum_h |hi-hj| Wc[h,k] + (hi*hj) Wd[h,k]   (tf32 GEMM, K=128)
//   e_k = relu(pair + Ai[i,k] + Bj[j,k]);  edge = relu(e@W4 + b4)
//   adapt = edge*prior + eye
// Block tile: M=256 edges (32i x 8j), N=64, K=128. 8 warps = 4 m x 2 n.
// grid (N/TJB, N/TIB, B), block 256.
// ---------------------------------------------------------------------------
__global__ __launch_bounds__(256)
void k_edge(const float* __restrict__ W4,
            const float* __restrict__ b4p,
            const float* __restrict__ coords,
            float* __restrict__ out) {
    __shared__ float s_hi[32][68];               // pad 68: conflict-free A builds
    __shared__ float s_hj[8][68];
    __shared__ float s_WfC[8][8][32][2];         // 16KB, reused as Ais later
    __shared__ float s_WfD[8][8][32][2];         // 16KB, reused as Bjs later
    __shared__ float s_part[2][256];
    __shared__ float s_ad[256];
    __shared__ float s_W4[64];
    __shared__ float s_ci[32][8];
    __shared__ float s_cj[8][8];

    const int tid = threadIdx.x;
    const int b   = blockIdx.z;
    const int i0  = blockIdx.y * TIB;
    const int j0  = blockIdx.x * TJB;
    const int bN  = b * N_;

    const float* reprB = g_repr + (size_t)bN * H_;

    // prologue
    for (int idx = tid; idx < 32 * 64; idx += 256)
        s_hi[idx >> 6][idx & 63] = reprB[(i0 + (idx >> 6)) * H_ + (idx & 63)];
    for (int idx = tid; idx < 8 * 64; idx += 256)
        s_hj[idx >> 6][idx & 63] = reprB[(j0 + (idx >> 6)) * H_ + (idx & 63)];
    {
        const float4* srcC = (const float4*)g_WfC;
        const float4* srcD = (const float4*)g_WfD;
        float4* dstC = (float4*)&s_WfC[0][0][0][0];
        float4* dstD = (float4*)&s_WfD[0][0][0][0];
        for (int idx = tid; idx < 1024; idx += 256) { dstC[idx] = srcC[idx]; dstD[idx] = srcD[idx]; }
    }
    if (tid < 64) s_W4[tid] = W4[tid];
    // coord tiles for inline prior
    s_ci[tid >> 3][tid & 7] = coords[(i0 + (tid >> 3)) * C_ + (tid & 7)];
    if (tid < 64) s_cj[tid >> 3][tid & 7] = coords[(j0 + (tid >> 3)) * C_ + (tid & 7)];
    __syncthreads();

    const int wid = tid >> 5, lane = tid & 31;
    const int warp_m = wid & 3;                  // edges [warp_m*64, +64)
    const int warp_n = wid >> 2;                 // k [warp_n*32, +32)
    const int g = lane >> 2, t = lane & 3;

    float acc[4][4][4];
    #pragma unroll
    for (int mt = 0; mt < 4; mt++)
        #pragma unroll
        for (int nt = 0; nt < 4; nt++)
            #pragma unroll
            for (int q = 0; q < 4; q++) acc[mt][nt][q] = 0.0f;

    #pragma unroll
    for (int hp = 0; hp < 8; hp++) {             // h-octet = K-step pair
        const int h0 = hp * 8 + t, h1 = h0 + 4;
        const float hj0 = s_hj[g][h0], hj1 = s_hj[g][h1];
        unsigned aD[4][4], aP[4][4];
        #pragma unroll
        for (int mt = 0; mt < 4; mt++) {
            const int il0 = warp_m * 8 + mt * 2;
            float hi00 = s_hi[il0][h0],     hi01 = s_hi[il0][h1];
            float hi10 = s_hi[il0 + 1][h0], hi11 = s_hi[il0 + 1][h1];
            aD[mt][0] = cvt_tf32(fabsf(hi00 - hj0));
            aD[mt][1] = cvt_tf32(fabsf(hi10 - hj0));
            aD[mt][2] = cvt_tf32(fabsf(hi01 - hj1));
            aD[mt][3] = cvt_tf32(fabsf(hi11 - hj1));
            aP[mt][0] = cvt_tf32(hi00 * hj0);
            aP[mt][1] = cvt_tf32(hi10 * hj0);
            aP[mt][2] = cvt_tf32(hi01 * hj1);
            aP[mt][3] = cvt_tf32(hi11 * hj1);
        }
        #pragma unroll
        for (int nt = 0; nt < 4; nt++) {
            const int ntg = warp_n * 4 + nt;
            float2 bc = *(const float2*)&s_WfC[hp][ntg][lane][0];
            float2 bd = *(const float2*)&s_WfD[hp][ntg][lane][0];
            unsigned bC[2] = { __float_as_uint(bc.x), __float_as_uint(bc.y) };
            unsigned bD[2] = { __float_as_uint(bd.x), __float_as_uint(bd.y) };
            #pragma unroll
            for (int mt = 0; mt < 4; mt++) {
                mma_tf32(acc[mt][nt], aD[mt], bC);
                mma_tf32(acc[mt][nt], aP[mt], bD);
            }
        }
    }

    // restage Ai/Bj into smem reused from the weight-fragment buffers
    __syncthreads();
    float* s_Ais = &s_WfC[0][0][0][0];           // [32][64]
    float* s_Bjs = &s_WfD[0][0][0][0];           // [8][64]
    {
        const float4* srcA = (const float4*)(g_Ai + (size_t)(bN + i0) * H_);
        float4* dstA = (float4*)s_Ais;
        for (int idx = tid; idx < 512; idx += 256) dstA[idx] = srcA[idx];
        const float4* srcB = (const float4*)(g_Bj + (size_t)(bN + j0) * H_);
        float4* dstB = (float4*)s_Bjs;
        if (tid < 128) dstB[tid] = srcB[tid];
    }
    __syncthreads();

    // epilogue: e_k = relu(acc + Ai + Bj); partial dot with W4 over this
    // thread's k columns, then quad-reduce (t lanes) and cross-warp_n combine.
    float psum[4][2];
    #pragma unroll
    for (int mt = 0; mt < 4; mt++) {
        #pragma unroll
        for (int half = 0; half < 2; half++) {
            const int il = warp_m * 8 + mt * 2 + half;
            const int jl = g;
            float s = 0.0f;
            #pragma unroll
            for (int nt = 0; nt < 4; nt++) {
                const int k0 = warp_n * 32 + nt * 8 + 2 * t;
                float ab0 = s_Ais[il * 64 + k0]     + s_Bjs[jl * 64 + k0];
                float ab1 = s_Ais[il * 64 + k0 + 1] + s_Bjs[jl * 64 + k0 + 1];
                float v0 = fmaxf(acc[mt][nt][half * 2]     + ab0, 0.0f);
                float v1 = fmaxf(acc[mt][nt][half * 2 + 1] + ab1, 0.0f);
                s += v0 * s_W4[k0] + v1 * s_W4[k0 + 1];
            }
            psum[mt][half] = s;
        }
    }
    #pragma unroll
    for (int mt = 0; mt < 4; mt++) {
        #pragma unroll
        for (int half = 0; half < 2; half++) {
            float s = psum[mt][half];
            s += __shfl_xor_sync(0xffffffffu, s, 1);
            s += __shfl_xor_sync(0xffffffffu, s, 2);
            if (t == 0) {
                int e = warp_m * 64 + mt * 16 + g + half * 8;
                s_part[warp_n][e] = s;
            }
        }
    }
    __syncthreads();

    {
        const float b4v = b4p[0];
        int e  = tid;                            // 0..255
        int il = e >> 3, jl = e & 7;
        int i  = i0 + il, j = j0 + jl;
        float edge = fmaxf(s_part[0][e] + s_part[1][e] + b4v, 0.0f);
        // inline prior: 1/(1+dist), zero on diagonal
        float d2 = 0.0f;
        #pragma unroll
        for (int c = 0; c < C_; c++) {
            float d = s_ci[il][c] - s_cj[jl][c];
            d2 += d * d;
        }
        float pr = (i == j) ? 0.0f : 1.0f / (1.0f + sqrtf(d2));
        float ad = edge * pr + ((i == j) ? 1.0f : 0.0f);
        out[((size_t)(bN + i)) * N_ + j] = ad;   // adapt (pre-normalization)
        s_ad[e] = ad;
    }
    __syncthreads();

    if (tid < 32) {
        float dsum = 0.0f;
        #pragma unroll
        for (int jl = 0; jl < 8; jl++) dsum += s_ad[tid * 8 + jl];
        atomicAdd(&g_deg[bN + i0 + tid], dsum);
    }
}

// ---------------------------------------------------------------------------
// K6: out *= inv_i * inv_j  with inline rsqrt (no separate invdeg pass)
// ---------------------------------------------------------------------------
__global__ void k_norm(float* __restrict__ out) {
    int idx = blockIdx.x * 256 + threadIdx.x;      // one float4 each
    int j4  = (idx & 127) * 4;                     // 128 quads per row
    int bi  = idx >> 7;                            // flat b*N+i, 0..1023
    float  inv_i = rsqrtf(fmaxf(g_deg[bi], 1e-6f));
    float4 dj    = *(const float4*)&g_deg[(bi & ~(N_ - 1)) + j4];
    float4 v = ((float4*)out)[idx];
    v.x *= inv_i * rsqrtf(fmaxf(dj.x, 1e-6f));
    v.y *= inv_i * rsqrtf(fmaxf(dj.y, 1e-6f));
    v.z *= inv_i * rsqrtf(fmaxf(dj.z, 1e-6f));
    v.w *= inv_i * rsqrtf(fmaxf(dj.w, 1e-6f));
    ((float4*)out)[idx] = v;
}

// ---------------------------------------------------------------------------
// launch
// ---------------------------------------------------------------------------
extern "C" void kernel_launch(void* const* d_in, const int* in_sizes, int n_in,
                              void* d_out, int out_size) {
    const float* x      = (const float*)d_in[0];
    const float* mask   = (const float*)d_in[1];
    const float* statc  = (const float*)d_in[2];
    const float* coords = (const float*)d_in[3];
    const float* W1     = (const float*)d_in[4];
    const float* b1     = (const float*)d_in[5];
    const float* W2     = (const float*)d_in[6];
    const float* b2     = (const float*)d_in[7];
    const float* W3     = (const float*)d_in[8];
    const float* b3     = (const float*)d_in[9];
    const float* W4     = (const float*)d_in[10];
    const float* b4     = (const float*)d_in[11];
    float* out = (float*)d_out;

    k_zero<<<2, 512>>>();
    k_wprep<<<16, 256>>>(W3);
    k_reduce<<<dim3(N_ / 32, B_, 8), dim3(32, 8)>>>(x, mask);
    k_finalize_mlp<<<dim3(N_ / 32, B_), dim3(32, 8)>>>(x, statc, W1, b1, W2, b2);
    k_aibj<<<(B_ * N_) / 16, 256>>>(W3, b3);
    k_edge<<<dim3(N_ / TJB, N_ / TIB, B_), 256>>>(W4, b4, coords, out);
    k_norm<<<(B_ * N_ * N_ / 4) / 256, 256>>>(out);
}

// round 9
// speedup vs baseline: 3.1059x; 1.0416x over previous
#include <cuda_runtime.h>
#include <cuda_bf16.h>

// Shapes (fixed by the problem)
#define B_  2
#define T_  512
#define N_  512
#define H_  64
#define S_  8
#define C_  8

// Edge-kernel tiling: block = 256 edges (32 i x 8 j), N=64 k, K=128
#define TIB 32
#define TJB 8

// ---------------------------------------------------------------------------
// tf32 helpers (sm_80+ PTX, valid on sm_103a)
// ---------------------------------------------------------------------------
__device__ __forceinline__ unsigned cvt_tf32(float f) {
    unsigned u;
    asm("cvt.rna.tf32.f32 %0, %1;" : "=r"(u) : "f"(f));
    return u;
}
__device__ __forceinline__ void mma_tf32(float* c, const unsigned* a, const unsigned* b) {
    asm("mma.sync.aligned.m16n8k8.row.col.f32.tf32.tf32.f32 "
        "{%0,%1,%2,%3}, {%4,%5,%6,%7}, {%8,%9}, {%0,%1,%2,%3};"
        : "+f"(c[0]), "+f"(c[1]), "+f"(c[2]), "+f"(c[3])
        : "r"(a[0]), "r"(a[1]), "r"(a[2]), "r"(a[3]), "r"(b[0]), "r"(b[1]));
}

// ---------------------------------------------------------------------------
// Device scratch (no allocations allowed)
// ---------------------------------------------------------------------------
__device__ float g_repr[B_ * N_ * H_];   // node_repr
__device__ float g_Ai  [B_ * N_ * H_];   // repr @ W3[0:64]   + b3
__device__ float g_Bj  [B_ * N_ * H_];   // repr @ W3[64:128]
__device__ float g_deg [B_ * N_];        // degree accumulators
// per-node reduction stats
__device__ float g_s_sum[B_ * N_];
__device__ float g_s_sq [B_ * N_];
__device__ float g_s_cnt[B_ * N_];
__device__ float g_s_ms [B_ * N_];
__device__ int   g_s_last[B_ * N_];
// W3c/W3d pre-converted to tf32 and pre-shuffled into mma B-fragment order:
// flat index = ((hp*8 + ntg)*32 + lane)*2 + p
__device__ float g_WfC[8 * 8 * 32 * 2];
__device__ float g_WfD[8 * 8 * 32 * 2];

// ---------------------------------------------------------------------------
// K0: init — zero accumulators (blocks 0..3) + W3c/W3d fragment prep (4..19).
// For m16n8k8.row.col B-frag: b0 at (row=lane%4, col=lane/4), b1 row+4.
// ---------------------------------------------------------------------------
__global__ void k_init(const float* __restrict__ W3) {
    if (blockIdx.x < 4) {
        int t = blockIdx.x * 256 + threadIdx.x;    // 0..1023
        g_deg[t] = 0.0f;
        g_s_sum[t] = 0.0f; g_s_sq[t] = 0.0f;
        g_s_cnt[t] = 0.0f; g_s_ms[t] = 0.0f;
        g_s_last[t] = 0;
    } else {
        int f = (blockIdx.x - 4) * 256 + threadIdx.x;  // 0..4095
        int p    = f & 1;
        int lane = (f >> 1) & 31;
        int ntg  = (f >> 6) & 7;
        int hp   = f >> 9;
        int row  = hp * 8 + (lane & 3) + p * 4;    // K index within [0,64)
        int col  = ntg * 8 + (lane >> 2);          // n index
        g_WfC[f] = __uint_as_float(cvt_tf32(W3[(128 + row) * 64 + col]));
        g_WfD[f] = __uint_as_float(cvt_tf32(W3[(192 + row) * 64 + col]));
    }
}

// ---------------------------------------------------------------------------
// K1a: chip-wide T-chunked reduction. grid (N/32, B, 8), block (32, 8).
// Each block covers 64 timesteps for 32 nodes; partials via atomics.
// ---------------------------------------------------------------------------
__global__ void k_reduce(const float* __restrict__ x,
                         const float* __restrict__ mask) {
    const int tx = threadIdx.x, ty = threadIdx.y;
    const int b  = blockIdx.y;
    const int n  = blockIdx.x * 32 + tx;
    const int t0 = blockIdx.z * 64;

    __shared__ float s_sum[8][33], s_sq[8][33], s_cnt[8][33], s_ms[8][33];
    __shared__ int   s_last[8][33];

    const float* xb = x    + (size_t)b * T_ * N_;
    const float* mb = mask + (size_t)b * T_ * N_;

    float sum = 0.f, sq = 0.f, cnt = 0.f, ms = 0.f;
    int   lastt = -1;
    #pragma unroll
    for (int it = 0; it < 8; it++) {
        int t = t0 + ty + it * 8;
        float xv = xb[t * N_ + n];
        float mv = mb[t * N_ + n];
        float ob = 1.0f - mv;
        sum += xv * ob;
        sq  += xv * xv * ob;
        cnt += ob;
        ms  += mv;
        if (ob > 0.5f) lastt = t;
    }
    s_sum[ty][tx] = sum; s_sq[ty][tx] = sq; s_cnt[ty][tx] = cnt;
    s_ms[ty][tx] = ms;   s_last[ty][tx] = lastt;
    __syncthreads();

    if (ty == 0) {
        for (int r = 1; r < 8; r++) {
            sum += s_sum[r][tx]; sq += s_sq[r][tx]; cnt += s_cnt[r][tx];
            ms  += s_ms[r][tx];
            lastt = max(lastt, s_last[r][tx]);
        }
        int idx = b * N_ + n;
        atomicAdd(&g_s_sum[idx], sum);
        atomicAdd(&g_s_sq [idx], sq);
        atomicAdd(&g_s_cnt[idx], cnt);
        atomicAdd(&g_s_ms [idx], ms);
        if (lastt >= 0) atomicMax(&g_s_last[idx], lastt);
    }
}

// ---------------------------------------------------------------------------
// K1b (fused): finalize stats -> feats -> layer1 -> layer2 -> Ai/Bj.
// grid 64 blocks x 16 nodes; block 256 = 16 nodes x 16 k-lanes (4 k each).
// Weights staged in a 32KB smem union: {W1,W2} first, then W3[a;b].
// ---------------------------------------------------------------------------
__global__ __launch_bounds__(256)
void k_node(const float* __restrict__ x,
            const float* __restrict__ statc,
            const float* __restrict__ W1,
            const float* __restrict__ b1,
            const float* __restrict__ W2,
            const float* __restrict__ b2,
            const float* __restrict__ W3,
            const float* __restrict__ b3) {
    __shared__ float s_w[128 * 64];      // 32KB union: [W1(768) W2(4096)] then W3ab(8192)
    __shared__ float s_f[16][13];        // feats
    __shared__ float s_h[16][65];        // hidden
    __shared__ float s_r[16][65];        // repr

    const int tid = threadIdx.x;
    const int ng0 = blockIdx.x * 16;     // flat (b*N + n) base; never straddles batch

    // stage W1 (12x64) then W2 (64x64)
    for (int idx = tid; idx < 768; idx += 256)  s_w[idx] = W1[idx];
    for (int idx = tid; idx < 4096; idx += 256) s_w[768 + idx] = W2[idx];

    // dynamic feats: one thread per node
    if (tid < 16) {
        int idx = ng0 + tid;
        int b = idx >> 9, n = idx & (N_ - 1);
        float sum = g_s_sum[idx], sq = g_s_sq[idx];
        float cnt = g_s_cnt[idx], ms = g_s_ms[idx];
        int lastt = g_s_last[idx];
        float count = fmaxf(cnt, 1.0f);
        float mean  = sum / count;
        float var   = (sq - 2.0f * mean * sum + mean * mean * cnt) / count;
        float stdv  = sqrtf(fmaxf(var, 0.0f) + 1e-6f);
        float last  = x[((size_t)b * T_ + lastt) * N_ + n];
        s_f[tid][0] = mean; s_f[tid][1] = stdv; s_f[tid][2] = last;
        s_f[tid][3] = ms * (1.0f / (float)T_);
    }
    // static feats: 128 threads
    if (tid < 128) {
        int nl = tid >> 3, s = tid & 7;
        s_f[nl][4 + s] = statc[((ng0 + nl) & (N_ - 1)) * S_ + s];
    }
    __syncthreads();

    const int nl = tid >> 4;             // node-in-block
    const int kl = tid & 15;             // k-lane

    // layer 1: feats(12) @ W1 -> relu
    #pragma unroll
    for (int kk = 0; kk < 4; kk++) {
        int k = kl + 16 * kk;            // conflict-free bank mapping
        float a = b1[k];
        #pragma unroll
        for (int f = 0; f < 12; f++) a += s_f[nl][f] * s_w[f * 64 + k];
        s_h[nl][k] = fmaxf(a, 0.0f);
    }
    __syncthreads();

    // layer 2: h(64) @ W2 -> relu -> repr (smem + global for k_edge)
    #pragma unroll
    for (int kk = 0; kk < 4; kk++) {
        int k = kl + 16 * kk;
        float a = b2[k];
        #pragma unroll
        for (int h = 0; h < 64; h++) a += s_h[nl][h] * s_w[768 + h * 64 + k];
        float r = fmaxf(a, 0.0f);
        s_r[nl][k] = r;
        g_repr[(ng0 + nl) * H_ + k] = r;
    }
    __syncthreads();

    // restage union with W3 rows 0..127 (a then b)
    for (int idx = tid; idx < 8192; idx += 256) s_w[idx] = W3[idx];
    __syncthreads();

    // Ai = repr@W3a + b3, Bj = repr@W3b
    #pragma unroll
    for (int kk = 0; kk < 4; kk++) {
        int k = kl + 16 * kk;
        float a = b3[k], bj = 0.0f;
        #pragma unroll
        for (int h = 0; h < 64; h++) {
            float r = s_r[nl][h];
            a  += r * s_w[h * 64 + k];
            bj += r * s_w[(64 + h) * 64 + k];
        }
        g_Ai[(ng0 + nl) * H_ + k] = a;
        g_Bj[(ng0 + nl) * H_ + k] = bj;
    }
}

// ---------------------------------------------------------------------------
// K4: edge MLP via tf32 mma.sync; prior computed inline from coords.
//   pair[e,k] = sum_h |hi-hj| Wc[h,k] + (hi*hj) Wd[h,k]   (tf32 GEMM, K=128)
//   e_k = relu(pair + Ai[i,k] + Bj[j,k]);  edge = relu(e@W4 + b4)
//   adapt = edge*prior + eye
// Block tile: M=256 edges (32i x 8j), N=64, K=128. 8 warps = 4 m x 2 n.
// grid (N/TJB, N/TIB, B), block 256.
// ---------------------------------------------------------------------------
__global__ __launch_bounds__(256)
void k_edge(const float* __restrict__ W4,
            const float* __restrict__ b4p,
            const float* __restrict__ coords,
            float* __restrict__ out) {
    __shared__ float s_hi[32][68];               // pad 68: conflict-free A builds
    __shared__ float s_hj[8][68];
    __shared__ float s_WfC[8][8][32][2];         // 16KB, reused as Ais later
    __shared__ float s_WfD[8][8][32][2];         // 16KB, reused as Bjs later
    __shared__ float s_part[2][256];
    __shared__ float s_ad[256];
    __shared__ float s_W4[64];
    __shared__ float s_ci[32][8];
    __shared__ float s_cj[8][8];

    const int tid = threadIdx.x;
    const int b   = blockIdx.z;
    const int i0  = blockIdx.y * TIB;
    const int j0  = blockIdx.x * TJB;
    const int bN  = b * N_;

    const float* reprB = g_repr + (size_t)bN * H_;

    // prologue
    for (int idx = tid; idx < 32 * 64; idx += 256)
        s_hi[idx >> 6][idx & 63] = reprB[(i0 + (idx >> 6)) * H_ + (idx & 63)];
    for (int idx = tid; idx < 8 * 64; idx += 256)
        s_hj[idx >> 6][idx & 63] = reprB[(j0 + (idx >> 6)) * H_ + (idx & 63)];
    {
        const float4* srcC = (const float4*)g_WfC;
        const float4* srcD = (const float4*)g_WfD;
        float4* dstC = (float4*)&s_WfC[0][0][0][0];
        float4* dstD = (float4*)&s_WfD[0][0][0][0];
        for (int idx = tid; idx < 1024; idx += 256) { dstC[idx] = srcC[idx]; dstD[idx] = srcD[idx]; }
    }
    if (tid < 64) s_W4[tid] = W4[tid];
    // coord tiles for inline prior
    s_ci[tid >> 3][tid & 7] = coords[(i0 + (tid >> 3)) * C_ + (tid & 7)];
    if (tid < 64) s_cj[tid >> 3][tid & 7] = coords[(j0 + (tid >> 3)) * C_ + (tid & 7)];
    __syncthreads();

    const int wid = tid >> 5, lane = tid & 31;
    const int warp_m = wid & 3;                  // edges [warp_m*64, +64)
    const int warp_n = wid >> 2;                 // k [warp_n*32, +32)
    const int g = lane >> 2, t = lane & 3;

    float acc[4][4][4];
    #pragma unroll
    for (int mt = 0; mt < 4; mt++)
        #pragma unroll
        for (int nt = 0; nt < 4; nt++)
            #pragma unroll
            for (int q = 0; q < 4; q++) acc[mt][nt][q] = 0.0f;

    #pragma unroll
    for (int hp = 0; hp < 8; hp++) {             // h-octet = K-step pair
        const int h0 = hp * 8 + t, h1 = h0 + 4;
        const float hj0 = s_hj[g][h0], hj1 = s_hj[g][h1];
        unsigned aD[4][4], aP[4][4];
        #pragma unroll
        for (int mt = 0; mt < 4; mt++) {
            const int il0 = warp_m * 8 + mt * 2;
            float hi00 = s_hi[il0][h0],     hi01 = s_hi[il0][h1];
            float hi10 = s_hi[il0 + 1][h0], hi11 = s_hi[il0 + 1][h1];
            aD[mt][0] = cvt_tf32(fabsf(hi00 - hj0));
            aD[mt][1] = cvt_tf32(fabsf(hi10 - hj0));
            aD[mt][2] = cvt_tf32(fabsf(hi01 - hj1));
            aD[mt][3] = cvt_tf32(fabsf(hi11 - hj1));
            aP[mt][0] = cvt_tf32(hi00 * hj0);
            aP[mt][1] = cvt_tf32(hi10 * hj0);
            aP[mt][2] = cvt_tf32(hi01 * hj1);
            aP[mt][3] = cvt_tf32(hi11 * hj1);
        }
        #pragma unroll
        for (int nt = 0; nt < 4; nt++) {
            const int ntg = warp_n * 4 + nt;
            float2 bc = *(const float2*)&s_WfC[hp][ntg][lane][0];
            float2 bd = *(const float2*)&s_WfD[hp][ntg][lane][0];
            unsigned bC[2] = { __float_as_uint(bc.x), __float_as_uint(bc.y) };
            unsigned bD[2] = { __float_as_uint(bd.x), __float_as_uint(bd.y) };
            #pragma unroll
            for (int mt = 0; mt < 4; mt++) {
                mma_tf32(acc[mt][nt], aD[mt], bC);
                mma_tf32(acc[mt][nt], aP[mt], bD);
            }
        }
    }

    // restage Ai/Bj into smem reused from the weight-fragment buffers
    __syncthreads();
    float* s_Ais = &s_WfC[0][0][0][0];           // [32][64]
    float* s_Bjs = &s_WfD[0][0][0][0];           // [8][64]
    {
        const float4* srcA = (const float4*)(g_Ai + (size_t)(bN + i0) * H_);
        float4* dstA = (float4*)s_Ais;
        for (int idx = tid; idx < 512; idx += 256) dstA[idx] = srcA[idx];
        const float4* srcB = (const float4*)(g_Bj + (size_t)(bN + j0) * H_);
        float4* dstB = (float4*)s_Bjs;
        if (tid < 128) dstB[tid] = srcB[tid];
    }
    __syncthreads();

    // epilogue: e_k = relu(acc + Ai + Bj); partial dot with W4 over this
    // thread's k columns, then quad-reduce (t lanes) and cross-warp_n combine.
    float psum[4][2];
    #pragma unroll
    for (int mt = 0; mt < 4; mt++) {
        #pragma unroll
        for (int half = 0; half < 2; half++) {
            const int il = warp_m * 8 + mt * 2 + half;
            const int jl = g;
            float s = 0.0f;
            #pragma unroll
            for (int nt = 0; nt < 4; nt++) {
                const int k0 = warp_n * 32 + nt * 8 + 2 * t;
                float ab0 = s_Ais[il * 64 + k0]     + s_Bjs[jl * 64 + k0];
                float ab1 = s_Ais[il * 64 + k0 + 1] + s_Bjs[jl * 64 + k0 + 1];
                float v0 = fmaxf(acc[mt][nt][half * 2]     + ab0, 0.0f);
                float v1 = fmaxf(acc[mt][nt][half * 2 + 1] + ab1, 0.0f);
                s += v0 * s_W4[k0] + v1 * s_W4[k0 + 1];
            }
            psum[mt][half] = s;
        }
    }
    #pragma unroll
    for (int mt = 0; mt < 4; mt++) {
        #pragma unroll
        for (int half = 0; half < 2; half++) {
            float s = psum[mt][half];
            s += __shfl_xor_sync(0xffffffffu, s, 1);
            s += __shfl_xor_sync(0xffffffffu, s, 2);
            if (t == 0) {
                int e = warp_m * 64 + mt * 16 + g + half * 8;
                s_part[warp_n][e] = s;
            }
        }
    }
    __syncthreads();

    {
        const float b4v = b4p[0];
        int e  = tid;                            // 0..255
        int il = e >> 3, jl = e & 7;
        int i  = i0 + il, j = j0 + jl;
        float edge = fmaxf(s_part[0][e] + s_part[1][e] + b4v, 0.0f);
        // inline prior: 1/(1+dist), zero on diagonal
        float d2 = 0.0f;
        #pragma unroll
        for (int c = 0; c < C_; c++) {
            float d = s_ci[il][c] - s_cj[jl][c];
            d2 += d * d;
        }
        float pr = (i == j) ? 0.0f : 1.0f / (1.0f + sqrtf(d2));
        float ad = edge * pr + ((i == j) ? 1.0f : 0.0f);
        out[((size_t)(bN + i)) * N_ + j] = ad;   // adapt (pre-normalization)
        s_ad[e] = ad;
    }
    __syncthreads();

    if (tid < 32) {
        float dsum = 0.0f;
        #pragma unroll
        for (int jl = 0; jl < 8; jl++) dsum += s_ad[tid * 8 + jl];
        atomicAdd(&g_deg[bN + i0 + tid], dsum);
    }
}

// ---------------------------------------------------------------------------
// K6: out *= inv_i * inv_j  with inline rsqrt (no separate invdeg pass)
// ---------------------------------------------------------------------------
__global__ void k_norm(float* __restrict__ out) {
    int idx = blockIdx.x * 256 + threadIdx.x;      // one float4 each
    int j4  = (idx & 127) * 4;                     // 128 quads per row
    int bi  = idx >> 7;                            // flat b*N+i, 0..1023
    float  inv_i = rsqrtf(fmaxf(g_deg[bi], 1e-6f));
    float4 dj    = *(const float4*)&g_deg[(bi & ~(N_ - 1)) + j4];
    float4 v = ((float4*)out)[idx];
    v.x *= inv_i * rsqrtf(fmaxf(dj.x, 1e-6f));
    v.y *= inv_i * rsqrtf(fmaxf(dj.y, 1e-6f));
    v.z *= inv_i * rsqrtf(fmaxf(dj.z, 1e-6f));
    v.w *= inv_i * rsqrtf(fmaxf(dj.w, 1e-6f));
    ((float4*)out)[idx] = v;
}

// ---------------------------------------------------------------------------
// launch
// ---------------------------------------------------------------------------
extern "C" void kernel_launch(void* const* d_in, const int* in_sizes, int n_in,
                              void* d_out, int out_size) {
    const float* x      = (const float*)d_in[0];
    const float* mask   = (const float*)d_in[1];
    const float* statc  = (const float*)d_in[2];
    const float* coords = (const float*)d_in[3];
    const float* W1     = (const float*)d_in[4];
    const float* b1     = (const float*)d_in[5];
    const float* W2     = (const float*)d_in[6];
    const float* b2     = (const float*)d_in[7];
    const float* W3     = (const float*)d_in[8];
    const float* b3     = (const float*)d_in[9];
    const float* W4     = (const float*)d_in[10];
    const float* b4     = (const float*)d_in[11];
    float* out = (float*)d_out;

    k_init<<<20, 256>>>(W3);
    k_reduce<<<dim3(N_ / 32, B_, 8), dim3(32, 8)>>>(x, mask);
    k_node<<<(B_ * N_) / 16, 256>>>(x, statc, W1, b1, W2, b2, W3, b3);
    k_edge<<<dim3(N_ / TJB, N_ / TIB, B_), 256>>>(W4, b4, coords, out);
    k_norm<<<(B_ * N_ * N_ / 4) / 256, 256>>>(out);
}

// round 10
// speedup vs baseline: 3.2689x; 1.0525x over previous
#include <cuda_runtime.h>
#include <cuda_bf16.h>

// Shapes (fixed by the problem)
#define B_  2
#define T_  512
#define N_  512
#define H_  64
#define S_  8
#define C_  8

// Edge-kernel tiling: block = 256 edges (32 i x 8 j), N=64 k, K=128
#define TIB 32
#define TJB 8

// ---------------------------------------------------------------------------
// tf32 helpers (sm_80+ PTX, valid on sm_103a)
// ---------------------------------------------------------------------------
__device__ __forceinline__ unsigned cvt_tf32(float f) {
    unsigned u;
    asm("cvt.rna.tf32.f32 %0, %1;" : "=r"(u) : "f"(f));
    return u;
}
__device__ __forceinline__ void mma_tf32(float* c, const unsigned* a, const unsigned* b) {
    asm("mma.sync.aligned.m16n8k8.row.col.f32.tf32.tf32.f32 "
        "{%0,%1,%2,%3}, {%4,%5,%6,%7}, {%8,%9}, {%0,%1,%2,%3};"
        : "+f"(c[0]), "+f"(c[1]), "+f"(c[2]), "+f"(c[3])
        : "r"(a[0]), "r"(a[1]), "r"(a[2]), "r"(a[3]), "r"(b[0]), "r"(b[1]));
}

// ---------------------------------------------------------------------------
// Device scratch (no allocations allowed)
// ---------------------------------------------------------------------------
__device__ float g_repr[B_ * N_ * H_];   // node_repr
__device__ float g_Ai  [B_ * N_ * H_];   // repr @ W3[0:64]   + b3
__device__ float g_Bj  [B_ * N_ * H_];   // repr @ W3[64:128]
__device__ float g_deg [B_ * N_];        // degree accumulators
// per-node reduction stats
__device__ float g_s_sum[B_ * N_];
__device__ float g_s_sq [B_ * N_];
__device__ float g_s_cnt[B_ * N_];
__device__ float g_s_ms [B_ * N_];
__device__ int   g_s_last[B_ * N_];
// W3c/W3d pre-converted to tf32 and pre-shuffled into mma B-fragment order:
// flat index = ((hp*8 + ntg)*32 + lane)*2 + p
__device__ float g_WfC[8 * 8 * 32 * 2];
__device__ float g_WfD[8 * 8 * 32 * 2];

// ---------------------------------------------------------------------------
// K0: init — zero accumulators (blocks 0..3) + W3c/W3d fragment prep (4..19).
// For m16n8k8.row.col B-frag: b0 at (row=lane%4, col=lane/4), b1 row+4.
// ---------------------------------------------------------------------------
__global__ void k_init(const float* __restrict__ W3) {
    if (blockIdx.x < 4) {
        int t = blockIdx.x * 256 + threadIdx.x;    // 0..1023
        g_deg[t] = 0.0f;
        g_s_sum[t] = 0.0f; g_s_sq[t] = 0.0f;
        g_s_cnt[t] = 0.0f; g_s_ms[t] = 0.0f;
        g_s_last[t] = 0;
    } else {
        int f = (blockIdx.x - 4) * 256 + threadIdx.x;  // 0..4095
        int p    = f & 1;
        int lane = (f >> 1) & 31;
        int ntg  = (f >> 6) & 7;
        int hp   = f >> 9;
        int row  = hp * 8 + (lane & 3) + p * 4;    // K index within [0,64)
        int col  = ntg * 8 + (lane >> 2);          // n index
        g_WfC[f] = __uint_as_float(cvt_tf32(W3[(128 + row) * 64 + col]));
        g_WfD[f] = __uint_as_float(cvt_tf32(W3[(192 + row) * 64 + col]));
    }
}

// ---------------------------------------------------------------------------
// K1a: chip-wide T-chunked reduction. grid (N/32, B, 8), block (32, 8).
// ---------------------------------------------------------------------------
__global__ void k_reduce(const float* __restrict__ x,
                         const float* __restrict__ mask) {
    const int tx = threadIdx.x, ty = threadIdx.y;
    const int b  = blockIdx.y;
    const int n  = blockIdx.x * 32 + tx;
    const int t0 = blockIdx.z * 64;

    __shared__ float s_sum[8][33], s_sq[8][33], s_cnt[8][33], s_ms[8][33];
    __shared__ int   s_last[8][33];

    const float* xb = x    + (size_t)b * T_ * N_;
    const float* mb = mask + (size_t)b * T_ * N_;

    float sum = 0.f, sq = 0.f, cnt = 0.f, ms = 0.f;
    int   lastt = -1;
    #pragma unroll
    for (int it = 0; it < 8; it++) {
        int t = t0 + ty + it * 8;
        float xv = xb[t * N_ + n];
        float mv = mb[t * N_ + n];
        float ob = 1.0f - mv;
        sum += xv * ob;
        sq  += xv * xv * ob;
        cnt += ob;
        ms  += mv;
        if (ob > 0.5f) lastt = t;
    }
    s_sum[ty][tx] = sum; s_sq[ty][tx] = sq; s_cnt[ty][tx] = cnt;
    s_ms[ty][tx] = ms;   s_last[ty][tx] = lastt;
    __syncthreads();

    if (ty == 0) {
        for (int r = 1; r < 8; r++) {
            sum += s_sum[r][tx]; sq += s_sq[r][tx]; cnt += s_cnt[r][tx];
            ms  += s_ms[r][tx];
            lastt = max(lastt, s_last[r][tx]);
        }
        int idx = b * N_ + n;
        atomicAdd(&g_s_sum[idx], sum);
        atomicAdd(&g_s_sq [idx], sq);
        atomicAdd(&g_s_cnt[idx], cnt);
        atomicAdd(&g_s_ms [idx], ms);
        if (lastt >= 0) atomicMax(&g_s_last[idx], lastt);
    }
}

// ---------------------------------------------------------------------------
// K1b (fused): finalize stats -> feats -> layer1 -> layer2 -> Ai/Bj.
// grid 64 blocks x 16 nodes; block 256 = 16 nodes x 16 k-lanes (4 k each).
// ---------------------------------------------------------------------------
__global__ __launch_bounds__(256)
void k_node(const float* __restrict__ x,
            const float* __restrict__ statc,
            const float* __restrict__ W1,
            const float* __restrict__ b1,
            const float* __restrict__ W2,
            const float* __restrict__ b2,
            const float* __restrict__ W3,
            const float* __restrict__ b3) {
    __shared__ float s_w[128 * 64];      // 32KB union: [W1(768) W2(4096)] then W3ab(8192)
    __shared__ float s_f[16][13];        // feats
    __shared__ float s_h[16][65];        // hidden
    __shared__ float s_r[16][65];        // repr

    const int tid = threadIdx.x;
    const int ng0 = blockIdx.x * 16;     // flat (b*N + n) base; never straddles batch

    for (int idx = tid; idx < 768; idx += 256)  s_w[idx] = W1[idx];
    for (int idx = tid; idx < 4096; idx += 256) s_w[768 + idx] = W2[idx];

    if (tid < 16) {
        int idx = ng0 + tid;
        int b = idx >> 9, n = idx & (N_ - 1);
        float sum = g_s_sum[idx], sq = g_s_sq[idx];
        float cnt = g_s_cnt[idx], ms = g_s_ms[idx];
        int lastt = g_s_last[idx];
        float count = fmaxf(cnt, 1.0f);
        float mean  = sum / count;
        float var   = (sq - 2.0f * mean * sum + mean * mean * cnt) / count;
        float stdv  = sqrtf(fmaxf(var, 0.0f) + 1e-6f);
        float last  = x[((size_t)b * T_ + lastt) * N_ + n];
        s_f[tid][0] = mean; s_f[tid][1] = stdv; s_f[tid][2] = last;
        s_f[tid][3] = ms * (1.0f / (float)T_);
    }
    if (tid < 128) {
        int nl = tid >> 3, s = tid & 7;
        s_f[nl][4 + s] = statc[((ng0 + nl) & (N_ - 1)) * S_ + s];
    }
    __syncthreads();

    const int nl = tid >> 4;             // node-in-block
    const int kl = tid & 15;             // k-lane

    #pragma unroll
    for (int kk = 0; kk < 4; kk++) {
        int k = kl + 16 * kk;
        float a = b1[k];
        #pragma unroll
        for (int f = 0; f < 12; f++) a += s_f[nl][f] * s_w[f * 64 + k];
        s_h[nl][k] = fmaxf(a, 0.0f);
    }
    __syncthreads();

    #pragma unroll
    for (int kk = 0; kk < 4; kk++) {
        int k = kl + 16 * kk;
        float a = b2[k];
        #pragma unroll
        for (int h = 0; h < 64; h++) a += s_h[nl][h] * s_w[768 + h * 64 + k];
        float r = fmaxf(a, 0.0f);
        s_r[nl][k] = r;
        g_repr[(ng0 + nl) * H_ + k] = r;
    }
    __syncthreads();

    for (int idx = tid; idx < 8192; idx += 256) s_w[idx] = W3[idx];
    __syncthreads();

    #pragma unroll
    for (int kk = 0; kk < 4; kk++) {
        int k = kl + 16 * kk;
        float a = b3[k], bj = 0.0f;
        #pragma unroll
        for (int h = 0; h < 64; h++) {
            float r = s_r[nl][h];
            a  += r * s_w[h * 64 + k];
            bj += r * s_w[(64 + h) * 64 + k];
        }
        g_Ai[(ng0 + nl) * H_ + k] = a;
        g_Bj[(ng0 + nl) * H_ + k] = bj;
    }
}

// ---------------------------------------------------------------------------
// K4: edge MLP via tf32 mma.sync; prior inline.
// Block tile: M=256 edges (32i x 8j), N=64, K=128.
// 8 warps = 8 m-groups (32 edges each), each warp covers FULL N=64:
//   - no duplicated A-fragment builds (was 2x with the 4m x 2n split)
//   - epilogue needs no cross-warp combine (quad shuffle completes the sum)
// A operands fed as raw fp32 (HW truncates to tf32/RZ) -> no cvt in mainloop.
// grid (N/TJB, N/TIB, B), block 256.
// ---------------------------------------------------------------------------
__global__ __launch_bounds__(256)
void k_edge(const float* __restrict__ W4,
            const float* __restrict__ b4p,
            const float* __restrict__ coords,
            float* __restrict__ out) {
    __shared__ float s_hi[32][68];               // pad 68: conflict-free A builds
    __shared__ float s_hj[8][68];
    __shared__ float s_WfC[8][8][32][2];         // 16KB, reused as Ais later
    __shared__ float s_WfD[8][8][32][2];         // 16KB, reused as Bjs later
    __shared__ float s_ed[256];                  // per-edge pre-b4 sums
    __shared__ float s_ad[256];
    __shared__ float s_W4[64];
    __shared__ float s_ci[32][8];
    __shared__ float s_cj[8][8];

    const int tid = threadIdx.x;
    const int b   = blockIdx.z;
    const int i0  = blockIdx.y * TIB;
    const int j0  = blockIdx.x * TJB;
    const int bN  = b * N_;

    const float* reprB = g_repr + (size_t)bN * H_;

    // prologue
    for (int idx = tid; idx < 32 * 64; idx += 256)
        s_hi[idx >> 6][idx & 63] = reprB[(i0 + (idx >> 6)) * H_ + (idx & 63)];
    for (int idx = tid; idx < 8 * 64; idx += 256)
        s_hj[idx >> 6][idx & 63] = reprB[(j0 + (idx >> 6)) * H_ + (idx & 63)];
    {
        const float4* srcC = (const float4*)g_WfC;
        const float4* srcD = (const float4*)g_WfD;
        float4* dstC = (float4*)&s_WfC[0][0][0][0];
        float4* dstD = (float4*)&s_WfD[0][0][0][0];
        for (int idx = tid; idx < 1024; idx += 256) { dstC[idx] = srcC[idx]; dstD[idx] = srcD[idx]; }
    }
    if (tid < 64) s_W4[tid] = W4[tid];
    s_ci[tid >> 3][tid & 7] = coords[(i0 + (tid >> 3)) * C_ + (tid & 7)];
    if (tid < 64) s_cj[tid >> 3][tid & 7] = coords[(j0 + (tid >> 3)) * C_ + (tid & 7)];
    __syncthreads();

    const int wid = tid >> 5, lane = tid & 31;   // warp = m-group of 32 edges
    const int g = lane >> 2, t = lane & 3;       // g = jl, t = k-col quad

    float acc[2][8][4];
    #pragma unroll
    for (int mt = 0; mt < 2; mt++)
        #pragma unroll
        for (int nt = 0; nt < 8; nt++)
            #pragma unroll
            for (int q = 0; q < 4; q++) acc[mt][nt][q] = 0.0f;

    #pragma unroll
    for (int hp = 0; hp < 8; hp++) {             // h-octet = K-step pair
        const int h0 = hp * 8 + t, h1 = h0 + 4;
        const float hj0 = s_hj[g][h0], hj1 = s_hj[g][h1];
        unsigned aD[2][4], aP[2][4];
        #pragma unroll
        for (int mt = 0; mt < 2; mt++) {
            const int il0 = wid * 4 + mt * 2;
            float hi00 = s_hi[il0][h0],     hi01 = s_hi[il0][h1];
            float hi10 = s_hi[il0 + 1][h0], hi11 = s_hi[il0 + 1][h1];
            // raw fp32 bits: tf32 mma truncates low mantissa (RZ)
            aD[mt][0] = __float_as_uint(fabsf(hi00 - hj0));
            aD[mt][1] = __float_as_uint(fabsf(hi10 - hj0));
            aD[mt][2] = __float_as_uint(fabsf(hi01 - hj1));
            aD[mt][3] = __float_as_uint(fabsf(hi11 - hj1));
            aP[mt][0] = __float_as_uint(hi00 * hj0);
            aP[mt][1] = __float_as_uint(hi10 * hj0);
            aP[mt][2] = __float_as_uint(hi01 * hj1);
            aP[mt][3] = __float_as_uint(hi11 * hj1);
        }
        #pragma unroll
        for (int nt = 0; nt < 8; nt++) {
            float2 bc = *(const float2*)&s_WfC[hp][nt][lane][0];
            float2 bd = *(const float2*)&s_WfD[hp][nt][lane][0];
            unsigned bC[2] = { __float_as_uint(bc.x), __float_as_uint(bc.y) };
            unsigned bD[2] = { __float_as_uint(bd.x), __float_as_uint(bd.y) };
            #pragma unroll
            for (int mt = 0; mt < 2; mt++) {
                mma_tf32(acc[mt][nt], aD[mt], bC);
                mma_tf32(acc[mt][nt], aP[mt], bD);
            }
        }
    }

    // restage Ai/Bj into smem reused from the weight-fragment buffers
    __syncthreads();
    float* s_Ais = &s_WfC[0][0][0][0];           // [32][64]
    float* s_Bjs = &s_WfD[0][0][0][0];           // [8][64]
    {
        const float4* srcA = (const float4*)(g_Ai + (size_t)(bN + i0) * H_);
        float4* dstA = (float4*)s_Ais;
        for (int idx = tid; idx < 512; idx += 256) dstA[idx] = srcA[idx];
        const float4* srcB = (const float4*)(g_Bj + (size_t)(bN + j0) * H_);
        float4* dstB = (float4*)s_Bjs;
        if (tid < 128) dstB[tid] = srcB[tid];
    }
    __syncthreads();

    // epilogue: e_k = relu(acc + Ai + Bj); dot with W4 over this thread's k
    // columns (nt x {2t,2t+1} covers all 64 k across the quad), quad-reduce.
    #pragma unroll
    for (int mt = 0; mt < 2; mt++) {
        #pragma unroll
        for (int half = 0; half < 2; half++) {
            const int il = wid * 4 + mt * 2 + half;
            const int jl = g;
            float s = 0.0f;
            #pragma unroll
            for (int nt = 0; nt < 8; nt++) {
                const int k0 = nt * 8 + 2 * t;
                float ab0 = s_Ais[il * 64 + k0]     + s_Bjs[jl * 64 + k0];
                float ab1 = s_Ais[il * 64 + k0 + 1] + s_Bjs[jl * 64 + k0 + 1];
                float v0 = fmaxf(acc[mt][nt][half * 2]     + ab0, 0.0f);
                float v1 = fmaxf(acc[mt][nt][half * 2 + 1] + ab1, 0.0f);
                s += v0 * s_W4[k0] + v1 * s_W4[k0 + 1];
            }
            s += __shfl_xor_sync(0xffffffffu, s, 1);
            s += __shfl_xor_sync(0xffffffffu, s, 2);
            if (t == 0) s_ed[wid * 32 + mt * 16 + half * 8 + g] = s;
        }
    }
    __syncthreads();

    {
        const float b4v = b4p[0];
        int e  = tid;                            // 0..255
        int il = e >> 3, jl = e & 7;
        int i  = i0 + il, j = j0 + jl;
        float edge = fmaxf(s_ed[e] + b4v, 0.0f);
        float d2 = 0.0f;
        #pragma unroll
        for (int c = 0; c < C_; c++) {
            float d = s_ci[il][c] - s_cj[jl][c];
            d2 += d * d;
        }
        float pr = (i == j) ? 0.0f : 1.0f / (1.0f + sqrtf(d2));
        float ad = edge * pr + ((i == j) ? 1.0f : 0.0f);
        out[((size_t)(bN + i)) * N_ + j] = ad;   // adapt (pre-normalization)
        s_ad[e] = ad;
    }
    __syncthreads();

    if (tid < 32) {
        float dsum = 0.0f;
        #pragma unroll
        for (int jl = 0; jl < 8; jl++) dsum += s_ad[tid * 8 + jl];
        atomicAdd(&g_deg[bN + i0 + tid], dsum);
    }
}

// ---------------------------------------------------------------------------
// K6: out *= inv_i * inv_j  with inline rsqrt
// ---------------------------------------------------------------------------
__global__ void k_norm(float* __restrict__ out) {
    int idx = blockIdx.x * 256 + threadIdx.x;      // one float4 each
    int j4  = (idx & 127) * 4;                     // 128 quads per row
    int bi  = idx >> 7;                            // flat b*N+i, 0..1023
    float  inv_i = rsqrtf(fmaxf(g_deg[bi], 1e-6f));
    float4 dj    = *(const float4*)&g_deg[(bi & ~(N_ - 1)) + j4];
    float4 v = ((float4*)out)[idx];
    v.x *= inv_i * rsqrtf(fmaxf(dj.x, 1e-6f));
    v.y *= inv_i * rsqrtf(fmaxf(dj.y, 1e-6f));
    v.z *= inv_i * rsqrtf(fmaxf(dj.z, 1e-6f));
    v.w *= inv_i * rsqrtf(fmaxf(dj.w, 1e-6f));
    ((float4*)out)[idx] = v;
}

// ---------------------------------------------------------------------------
// launch
// ---------------------------------------------------------------------------
extern "C" void kernel_launch(void* const* d_in, const int* in_sizes, int n_in,
                              void* d_out, int out_size) {
    const float* x      = (const float*)d_in[0];
    const float* mask   = (const float*)d_in[1];
    const float* statc  = (const float*)d_in[2];
    const float* coords = (const float*)d_in[3];
    const float* W1     = (const float*)d_in[4];
    const float* b1     = (const float*)d_in[5];
    const float* W2     = (const float*)d_in[6];
    const float* b2     = (const float*)d_in[7];
    const float* W3     = (const float*)d_in[8];
    const float* b3     = (const float*)d_in[9];
    const float* W4     = (const float*)d_in[10];
    const float* b4     = (const float*)d_in[11];
    float* out = (float*)d_out;

    k_init<<<20, 256>>>(W3);
    k_reduce<<<dim3(N_ / 32, B_, 8), dim3(32, 8)>>>(x, mask);
    k_node<<<(B_ * N_) / 16, 256>>>(x, statc, W1, b1, W2, b2, W3, b3);
    k_edge<<<dim3(N_ / TJB, N_ / TIB, B_), 256>>>(W4, b4, coords, out);
    k_norm<<<(B_ * N_ * N_ / 4) / 256, 256>>>(out);
}